// round 4
// baseline (speedup 1.0000x reference)
#include <cuda_runtime.h>
#include <cuda_bf16.h>
#include <math.h>

// Problem constants
#define BATCH   4
#define SEQ     8192
#define DMODEL  1024
#define DREC    1024
#define N3      3072
#define CHUNK   64
#define NCHUNK  128            // SEQ / CHUNK
#define MROWS   (BATCH*SEQ)    // 32768

// ---------------------------------------------------------------------------
// Scratch (allocation-free: __device__ globals)
// ---------------------------------------------------------------------------
__device__ float g_aiv[(size_t)MROWS * N3];      // 402 MB
__device__ float g_a  [(size_t)MROWS * DREC];    // 134 MB
__device__ float g_s  [(size_t)MROWS * DREC];    // 134 MB
__device__ float g_h  [(size_t)MROWS * DREC];    // 134 MB
__device__ float g_cf [BATCH * NCHUNK * DREC];   // chunk final state
__device__ float g_cdk[BATCH * NCHUNK * DREC];   // chunk total decay
__device__ float g_inc[BATCH * NCHUNK * DREC];   // incoming state per chunk

// ---------------------------------------------------------------------------
// Packed f32x2 helpers (sm_103a double-rate fp32; PTX-only, ptxas won't fuse)
// ---------------------------------------------------------------------------
__device__ __forceinline__ unsigned long long f2pack(float lo, float hi) {
    unsigned long long r;
    asm("mov.b64 %0, {%1, %2};" : "=l"(r) : "f"(lo), "f"(hi));
    return r;
}
__device__ __forceinline__ void f2unpack(unsigned long long p, float& lo, float& hi) {
    asm("mov.b64 {%0, %1}, %2;" : "=f"(lo), "=f"(hi) : "l"(p));
}
__device__ __forceinline__ unsigned long long f2fma(unsigned long long a,
                                                    unsigned long long b,
                                                    unsigned long long c) {
    unsigned long long d;
    asm("fma.rn.f32x2 %0, %1, %2, %3;" : "=l"(d) : "l"(a), "l"(b), "l"(c));
    return d;
}

// ---------------------------------------------------------------------------
// SGEMM: C[M,N] = A[M,K] * B[K,N] (+ bias). 128x128x16 tile, 8x8/thread,
// double-buffered SMEM, FFMA2 inner product. Dims must divide tiles (they do).
// ---------------------------------------------------------------------------
#define BM 128
#define BN 128
#define BKK 16
#define SPAD 132   // 132*4 = 528 bytes, keeps 16B alignment, eases bank conflicts

template<bool BIAS>
__global__ __launch_bounds__(256, 2)
void sgemm_kernel(const float* __restrict__ A, const float* __restrict__ B,
                  const float* __restrict__ bias, float* __restrict__ C,
                  int M, int N, int K)
{
    __shared__ float As[2][BKK][SPAD];
    __shared__ float Bs[2][BKK][SPAD];

    const int tid = threadIdx.x;
    const int bx = blockIdx.x, by = blockIdx.y;
    const int tx = tid & 15, ty = tid >> 4;

    const int aRow = tid >> 2;        // 0..63
    const int aCol = (tid & 3) * 4;   // 0,4,8,12
    const int bRow = tid >> 5;        // 0..7
    const int bCol = (tid & 31) * 4;  // 0..124

    const float* Ag = A + (size_t)(by * BM + aRow) * K + aCol;
    const float* Bg = B + (size_t)bRow * N + (size_t)bx * BN + bCol;

    float4 ra[2], rb[2];
    // prologue: tile 0 -> buffer 0
    ra[0] = *(const float4*)(Ag);
    ra[1] = *(const float4*)(Ag + (size_t)64 * K);
    rb[0] = *(const float4*)(Bg);
    rb[1] = *(const float4*)(Bg + (size_t)8 * N);
#pragma unroll
    for (int r = 0; r < 2; r++) {
        As[0][aCol + 0][aRow + r * 64] = (r == 0 ? ra[0].x : ra[1].x);
        As[0][aCol + 1][aRow + r * 64] = (r == 0 ? ra[0].y : ra[1].y);
        As[0][aCol + 2][aRow + r * 64] = (r == 0 ? ra[0].z : ra[1].z);
        As[0][aCol + 3][aRow + r * 64] = (r == 0 ? ra[0].w : ra[1].w);
        *(float4*)&Bs[0][bRow + r * 8][bCol] = (r == 0 ? rb[0] : rb[1]);
    }
    __syncthreads();

    unsigned long long acc[8][4];
#pragma unroll
    for (int i = 0; i < 8; i++)
#pragma unroll
        for (int j = 0; j < 4; j++) acc[i][j] = 0ull;

    const int nT = K / BKK;
    for (int t = 0; t < nT; t++) {
        const int cur = t & 1, nxt = cur ^ 1;
        if (t + 1 < nT) {
            const float* Ag2 = Ag + (size_t)(t + 1) * BKK;
            const float* Bg2 = Bg + (size_t)(t + 1) * BKK * N;
            ra[0] = *(const float4*)(Ag2);
            ra[1] = *(const float4*)(Ag2 + (size_t)64 * K);
            rb[0] = *(const float4*)(Bg2);
            rb[1] = *(const float4*)(Bg2 + (size_t)8 * N);
        }
#pragma unroll
        for (int k = 0; k < BKK; k++) {
            float4 a03 = *(const float4*)&As[cur][k][ty * 8];
            float4 a47 = *(const float4*)&As[cur][k][ty * 8 + 4];
            ulonglong2 b01 = *(const ulonglong2*)&Bs[cur][k][tx * 8];
            ulonglong2 b23 = *(const ulonglong2*)&Bs[cur][k][tx * 8 + 4];
            unsigned long long bb[4] = {b01.x, b01.y, b23.x, b23.y};
            float av[8] = {a03.x, a03.y, a03.z, a03.w, a47.x, a47.y, a47.z, a47.w};
#pragma unroll
            for (int i = 0; i < 8; i++) {
                unsigned long long aa = f2pack(av[i], av[i]);
#pragma unroll
                for (int j = 0; j < 4; j++) acc[i][j] = f2fma(aa, bb[j], acc[i][j]);
            }
        }
        if (t + 1 < nT) {
#pragma unroll
            for (int r = 0; r < 2; r++) {
                As[nxt][aCol + 0][aRow + r * 64] = (r == 0 ? ra[0].x : ra[1].x);
                As[nxt][aCol + 1][aRow + r * 64] = (r == 0 ? ra[0].y : ra[1].y);
                As[nxt][aCol + 2][aRow + r * 64] = (r == 0 ? ra[0].z : ra[1].z);
                As[nxt][aCol + 3][aRow + r * 64] = (r == 0 ? ra[0].w : ra[1].w);
                *(float4*)&Bs[nxt][bRow + r * 8][bCol] = (r == 0 ? rb[0] : rb[1]);
            }
        }
        __syncthreads();
    }

    const int row0 = by * BM + ty * 8;
    const int col0 = bx * BN + tx * 8;
#pragma unroll
    for (int i = 0; i < 8; i++) {
        float out[8];
#pragma unroll
        for (int j = 0; j < 4; j++) f2unpack(acc[i][j], out[2 * j], out[2 * j + 1]);
        if (BIAS) {
#pragma unroll
            for (int j = 0; j < 8; j++) out[j] += bias[col0 + j];
        }
        float* cp = C + (size_t)(row0 + i) * N + col0;
        *(float4*)cp       = make_float4(out[0], out[1], out[2], out[3]);
        *(float4*)(cp + 4) = make_float4(out[4], out[5], out[6], out[7]);
    }
}

// ---------------------------------------------------------------------------
// Activation: a = sigmoid(ap + bias), i = sigmoid(ip),
//             s = sqrt(max(1 - a*a, 1e-8)) * (i * v)
// ---------------------------------------------------------------------------
__device__ __forceinline__ float sigmoidf_(float z) {
    return 1.0f / (1.0f + expf(-z));
}

__global__ __launch_bounds__(256)
void act_kernel(const float* __restrict__ aiv, const float* __restrict__ bias,
                float* __restrict__ Aout, float* __restrict__ Sout)
{
    size_t vid = (size_t)blockIdx.x * blockDim.x + threadIdx.x;  // float4 index
    size_t idx = vid * 4;                                        // element index in [MROWS*DREC]
    size_t r = idx >> 10;
    int d = (int)(idx & 1023);

    const float4 ap = *(const float4*)&aiv[r * N3 + d];
    const float4 ip = *(const float4*)&aiv[r * N3 + 1024 + d];
    const float4 vv = *(const float4*)&aiv[r * N3 + 2048 + d];
    const float4 bb = *(const float4*)&bias[d];

    float4 a4, s4;
    {
        float a = sigmoidf_(ap.x + bb.x), i = sigmoidf_(ip.x);
        a4.x = a; s4.x = sqrtf(fmaxf(1.0f - a * a, 1e-8f)) * (i * vv.x);
    }
    {
        float a = sigmoidf_(ap.y + bb.y), i = sigmoidf_(ip.y);
        a4.y = a; s4.y = sqrtf(fmaxf(1.0f - a * a, 1e-8f)) * (i * vv.y);
    }
    {
        float a = sigmoidf_(ap.z + bb.z), i = sigmoidf_(ip.z);
        a4.z = a; s4.z = sqrtf(fmaxf(1.0f - a * a, 1e-8f)) * (i * vv.z);
    }
    {
        float a = sigmoidf_(ap.w + bb.w), i = sigmoidf_(ip.w);
        a4.w = a; s4.w = sqrtf(fmaxf(1.0f - a * a, 1e-8f)) * (i * vv.w);
    }
    *(float4*)&Aout[idx] = a4;
    *(float4*)&Sout[idx] = s4;
}

// ---------------------------------------------------------------------------
// Scan pass A: per (b, chunk, d) compute chunk_total_decay and
// chunk_final_state, replicating the reference's clamped math exactly.
// ---------------------------------------------------------------------------
__global__ __launch_bounds__(256)
void scan_chunk_kernel(const float* __restrict__ A, const float* __restrict__ S,
                       float* __restrict__ cf, float* __restrict__ cdk)
{
    int d = blockIdx.x * 256 + threadIdx.x;   // 0..1023
    int chunk = blockIdx.y;
    int b = blockIdx.z;
    size_t base = ((size_t)(b * SEQ + chunk * CHUNK)) * DREC + d;

    float cl = 0.0f, cw = 0.0f, cd = 1.0f;
#pragma unroll 4
    for (int t = 0; t < CHUNK; t++) {
        float a = A[base + (size_t)t * DREC];
        float s = S[base + (size_t)t * DREC];
        cl += logf(fmaxf(a, 1e-10f));
        cd = expf(cl);
        cw += s / fmaxf(cd, 1e-10f);
    }
    int ci = (b * NCHUNK + chunk) * DREC + d;
    cdk[ci] = cd;
    cf[ci]  = cd * cw;   // intra_state at last step of chunk
}

// ---------------------------------------------------------------------------
// Scan pass B: sequential inter-chunk scan per (b, d); writes incoming_state
// for each chunk (clamped exactly as the reference).
// ---------------------------------------------------------------------------
__global__ __launch_bounds__(256)
void scan_inter_kernel(const float* __restrict__ cf, const float* __restrict__ cdk,
                       float* __restrict__ inc)
{
    int id = blockIdx.x * 256 + threadIdx.x;  // 0..4095
    int b = id >> 10;
    int d = id & 1023;

    float clc = 0.0f, ccd = 1.0f, cwc = 0.0f;
    for (int n = 0; n < NCHUNK; n++) {
        int ci = (b * NCHUNK + n) * DREC + d;
        inc[ci] = ccd * cwc;   // n=0 -> 1*0 = 0
        clc += logf(fmaxf(cdk[ci], 1e-10f));
        ccd = expf(clc);
        cwc += cf[ci] / fmaxf(ccd, 1e-10f);
    }
}

// ---------------------------------------------------------------------------
// Scan pass C: replay chunk scan, add cross-chunk contribution, write h.
// h[t] = cum_decay[t]*cumsum(weighted)[t] + cum_decay[t]*incoming_state
// ---------------------------------------------------------------------------
__global__ __launch_bounds__(256)
void scan_final_kernel(const float* __restrict__ A, const float* __restrict__ S,
                       const float* __restrict__ inc, float* __restrict__ H)
{
    int d = blockIdx.x * 256 + threadIdx.x;
    int chunk = blockIdx.y;
    int b = blockIdx.z;
    size_t base = ((size_t)(b * SEQ + chunk * CHUNK)) * DREC + d;
    float in = inc[(b * NCHUNK + chunk) * DREC + d];

    float cl = 0.0f, cw = 0.0f;
#pragma unroll 4
    for (int t = 0; t < CHUNK; t++) {
        float a = A[base + (size_t)t * DREC];
        float s = S[base + (size_t)t * DREC];
        cl += logf(fmaxf(a, 1e-10f));
        float cd = expf(cl);
        cw += s / fmaxf(cd, 1e-10f);
        H[base + (size_t)t * DREC] = cd * cw + cd * in;
    }
}

// ---------------------------------------------------------------------------
// Launch
// ---------------------------------------------------------------------------
extern "C" void kernel_launch(void* const* d_in, const int* in_sizes, int n_in,
                              void* d_out, int out_size)
{
    const float* x      = (const float*)d_in[0];  // [4,8192,1024]
    const float* W_aiv  = (const float*)d_in[1];  // [1024,3072]
    const float* d_bias = (const float*)d_in[2];  // [1024]
    const float* W_mix  = (const float*)d_in[3];  // [1024,1024]
    const float* b_mix  = (const float*)d_in[4];  // [1024]
    float* out = (float*)d_out;

    float *p_aiv, *p_a, *p_s, *p_h, *p_cf, *p_cdk, *p_inc;
    cudaGetSymbolAddress((void**)&p_aiv, g_aiv);
    cudaGetSymbolAddress((void**)&p_a,   g_a);
    cudaGetSymbolAddress((void**)&p_s,   g_s);
    cudaGetSymbolAddress((void**)&p_h,   g_h);
    cudaGetSymbolAddress((void**)&p_cf,  g_cf);
    cudaGetSymbolAddress((void**)&p_cdk, g_cdk);
    cudaGetSymbolAddress((void**)&p_inc, g_inc);

    // 1) aiv = x @ W_aiv
    {
        dim3 grid(N3 / BN, MROWS / BM);
        sgemm_kernel<false><<<grid, 256>>>(x, W_aiv, nullptr, p_aiv,
                                           MROWS, N3, DMODEL);
    }
    // 2) activations -> a, s
    {
        int nvec = (MROWS * DREC) / 4;               // 8,388,608
        act_kernel<<<nvec / 256, 256>>>(p_aiv, d_bias, p_a, p_s);
    }
    // 3) per-chunk summaries
    {
        dim3 grid(DREC / 256, NCHUNK, BATCH);
        scan_chunk_kernel<<<grid, 256>>>(p_a, p_s, p_cf, p_cdk);
    }
    // 4) inter-chunk scan
    scan_inter_kernel<<<(BATCH * DREC) / 256, 256>>>(p_cf, p_cdk, p_inc);
    // 5) replay + cross contribution -> h
    {
        dim3 grid(DREC / 256, NCHUNK, BATCH);
        scan_final_kernel<<<grid, 256>>>(p_a, p_s, p_inc, p_h);
    }
    // 6) out = h @ W_mix + b_mix
    {
        dim3 grid(DREC / BN, MROWS / BM);
        sgemm_kernel<true><<<grid, 256>>>(p_h, W_mix, b_mix, out,
                                          MROWS, DREC, DMODEL);
    }
}

// round 9
// speedup vs baseline: 4.0348x; 4.0348x over previous
#include <cuda_runtime.h>
#include <cuda_bf16.h>
#include <math.h>

// ---------------------------------------------------------------------------
// Arch-specific feature gate: tcgen05 is only legal in the sm_103a ("a")
// compilation pass. The harness also emits a plain compute_103 PTX pass,
// which must not see any tcgen05 text.
// ---------------------------------------------------------------------------
#ifndef __CUDA_ARCH_HAS_FEATURE__
#define __CUDA_ARCH_HAS_FEATURE__(x) 0
#endif
#if defined(__CUDA_ARCH_FEAT_SM103_ALL) || defined(__CUDA_ARCH_FEAT_SM100_ALL) || \
    defined(__CUDA_ARCH_SPECIFIC__) || __CUDA_ARCH_HAS_FEATURE__(SM103_ALL)
#define HAS_TCGEN05 1
#else
#define HAS_TCGEN05 0
#endif

// Problem constants
#define BATCH   4
#define SEQ     8192
#define DMODEL  1024
#define DREC    1024
#define N3      3072
#define CHUNK   64
#define NCHUNK  128
#define MROWS   (BATCH*SEQ)    // 32768

// ---------------------------------------------------------------------------
// Scratch (allocation-free: __device__ globals)
// ---------------------------------------------------------------------------
__device__ float g_aiv[(size_t)MROWS * N3];              // 402 MB fp32
__device__ float g_a  [(size_t)MROWS * DREC];            // 134 MB
__device__ float g_s  [(size_t)MROWS * DREC];            // 134 MB
__device__ __nv_bfloat16 g_xhi[(size_t)MROWS * DMODEL];  // 67 MB
__device__ __nv_bfloat16 g_xlo[(size_t)MROWS * DMODEL];
__device__ __nv_bfloat16 g_hhi[(size_t)MROWS * DREC];
__device__ __nv_bfloat16 g_hlo[(size_t)MROWS * DREC];
__device__ __nv_bfloat16 g_w1hi[(size_t)N3 * DMODEL];    // W_aiv^T [N3,K]
__device__ __nv_bfloat16 g_w1lo[(size_t)N3 * DMODEL];
__device__ __nv_bfloat16 g_w2hi[(size_t)DREC * DMODEL];  // W_mix^T [DREC,K]
__device__ __nv_bfloat16 g_w2lo[(size_t)DREC * DMODEL];
__device__ float g_cf [BATCH * NCHUNK * DREC];
__device__ float g_cdk[BATCH * NCHUNK * DREC];
__device__ float g_inc[BATCH * NCHUNK * DREC];

// ---------------------------------------------------------------------------
// Generic helpers (legal on all targets)
// ---------------------------------------------------------------------------
__device__ __forceinline__ unsigned smem_u32(const void* p) {
    unsigned a;
    asm("{ .reg .u64 t; cvta.to.shared.u64 t, %1; cvt.u32.u64 %0, t; }"
        : "=r"(a) : "l"(p));
    return a;
}

#define MBARRIER_INIT(mb, cnt) \
    asm volatile("mbarrier.init.shared.b64 [%0], %1;" \
                 :: "r"((unsigned)(mb)), "r"((unsigned)(cnt)) : "memory")

#define MBARRIER_INVAL(mb) \
    asm volatile("mbarrier.inval.shared.b64 [%0];" \
                 :: "r"((unsigned)(mb)) : "memory")

#define MBARRIER_WAIT_PARITY(mb, par) do { \
    unsigned _mb = (unsigned)(mb), _p = (unsigned)(par), _done; \
    asm volatile("{ .reg .pred p; mbarrier.try_wait.parity.acquire.cta.shared::cta.b64 p, [%1], %2; selp.b32 %0, 1, 0, p; }" \
                 : "=r"(_done) : "r"(_mb), "r"(_p) : "memory"); \
    if (!_done) { \
        asm volatile("{ .reg .pred P1; WL%=: mbarrier.try_wait.parity.acquire.cta.shared::cta.b64 P1, [%0], %1, 0x989680; @P1 bra.uni WD%=; bra.uni WL%=; WD%=: }" \
                     :: "r"(_mb), "r"(_p) : "memory"); \
    } \
} while (0)

#define FENCE_PROXY_ASYNC() asm volatile("fence.proxy.async.shared::cta;" ::: "memory")

// SW128 swizzle on byte offsets within a 1024B-aligned tile
#define SW128(o) ((o) ^ (((o) >> 3) & 0x70))

// ---------------------------------------------------------------------------
// tcgen05 helpers — ONLY compiled in the arch-specific pass
// ---------------------------------------------------------------------------
#if HAS_TCGEN05

__device__ __forceinline__ unsigned elect_one_pred() {
    unsigned pred;
    asm volatile("{ .reg .pred p; elect.sync _|p, 0xFFFFFFFF; selp.b32 %0, 1, 0, p; }"
                 : "=r"(pred));
    return pred;
}

#define TCGEN05_ALLOC(sm, n) \
    asm volatile("tcgen05.alloc.cta_group::1.sync.aligned.shared::cta.b32 [%0], %1;" \
                 :: "r"((unsigned)(sm)), "r"((unsigned)(n)) : "memory")
#define TCGEN05_DEALLOC(tm, n) \
    asm volatile("tcgen05.dealloc.cta_group::1.sync.aligned.b32 %0, %1;" \
                 :: "r"(tm), "r"((unsigned)(n)))
#define TCGEN05_RELINQ() \
    asm volatile("tcgen05.relinquish_alloc_permit.cta_group::1.sync.aligned;")
#define TCGEN05_COMMIT(mb) \
    asm volatile("tcgen05.commit.cta_group::1.mbarrier::arrive::one.shared::cluster.b64 [%0];" \
                 :: "r"((unsigned)(mb)) : "memory")
#define TCGEN05_FENCE_AFTER()  asm volatile("tcgen05.fence::after_thread_sync;"  ::: "memory")
#define TCGEN05_FENCE_BEFORE() asm volatile("tcgen05.fence::before_thread_sync;" ::: "memory")
#define TCGEN05_WAIT_LD()      asm volatile("tcgen05.wait::ld.sync.aligned;" ::: "memory")

#define TCGEN05_LD_X32(r, tm) \
    asm volatile("tcgen05.ld.sync.aligned.32x32b.x32.b32 " \
        "{%0, %1, %2, %3, %4, %5, %6, %7, %8, %9, %10, %11, %12, %13, %14, %15, " \
        " %16, %17, %18, %19, %20, %21, %22, %23, %24, %25, %26, %27, %28, %29, %30, %31}, [%32];" \
        : "=r"((r)[0]),  "=r"((r)[1]),  "=r"((r)[2]),  "=r"((r)[3]), \
          "=r"((r)[4]),  "=r"((r)[5]),  "=r"((r)[6]),  "=r"((r)[7]), \
          "=r"((r)[8]),  "=r"((r)[9]),  "=r"((r)[10]), "=r"((r)[11]), \
          "=r"((r)[12]), "=r"((r)[13]), "=r"((r)[14]), "=r"((r)[15]), \
          "=r"((r)[16]), "=r"((r)[17]), "=r"((r)[18]), "=r"((r)[19]), \
          "=r"((r)[20]), "=r"((r)[21]), "=r"((r)[22]), "=r"((r)[23]), \
          "=r"((r)[24]), "=r"((r)[25]), "=r"((r)[26]), "=r"((r)[27]), \
          "=r"((r)[28]), "=r"((r)[29]), "=r"((r)[30]), "=r"((r)[31]) \
        : "r"(tm))

// 64-bit SMEM descriptor: SW128, Blackwell v1, LBO=1, SBO=64 (8 rows x 128B atom)
__device__ __forceinline__ unsigned long long make_desc(unsigned addr) {
    const unsigned long long base =
        (2ull << 61) | (1ull << 46) | (64ull << 32) | (1ull << 16);
    return base | ((unsigned long long)(addr >> 4) & 0x3FFF);
}

// cg1 SS bf16 MMA: D[128,128] += A[128,16] * B[128,16]^T, fp32 accum
// idesc: F32 out (1<<4), BF16 A (1<<7), BF16 B (1<<10), N/8<<17, M/16<<24
#define MMA_IDESC 0x8200490u   // M=128 (8<<24), N=128 (16<<17)

__device__ __forceinline__ void mma_ss(unsigned d, unsigned long long a,
                                       unsigned long long b, unsigned acc) {
    asm volatile(
        "{\n\t"
        ".reg .pred p;\n\t"
        "setp.ne.u32 p, %4, 0;\n\t"
        "tcgen05.mma.cta_group::1.kind::f16 [%0], %1, %2, %3, {%5, %5, %5, %5}, p;\n\t"
        "}"
        :: "r"(d), "l"(a), "l"(b), "r"(MMA_IDESC), "r"(acc), "r"(0u)
        : "memory");
}

#endif  // HAS_TCGEN05

// ---------------------------------------------------------------------------
// bf16x3 GEMM: C[M,N] = (Ahi+Alo)[M,K] @ (Bhi+Blo)[N,K]^T (+ bias)
// Tile: 128(M) x 256(N), K-block 64, double-buffered SMEM, cg1 tcgen05.
//
// Pipelining discipline: ONE commit per K-block, and the wait for phase t is
// issued in iteration t (parity t&1), BEFORE commit t+1 exists. This keeps
// at most one un-consumed phase in flight — parity waits are unambiguous.
// (Waiting on phase t-1 after committing phase t deadlocks when the MMA
// engine completes both: stored parity re-aliases to the requested parity.)
// ---------------------------------------------------------------------------
#define GKB   64
#define GST   98304   // per-stage SMEM bytes: Ahi16K + Alo16K + Bhi32K + Blo32K
#define GSMEM (1024 + 1024 + 2*GST)   // align slack + header + 2 stages

template<bool BIAS>
__global__ __launch_bounds__(256, 1)
#if HAS_TCGEN05
__cluster_dims__(1, 1, 1)
#endif
void gemm_bf16x3_kernel(const __nv_bfloat16* __restrict__ Ahi,
                        const __nv_bfloat16* __restrict__ Alo,
                        const __nv_bfloat16* __restrict__ Bhi,
                        const __nv_bfloat16* __restrict__ Blo,
                        const float* __restrict__ bias,
                        float* __restrict__ C,
                        int K, int ldC)
{
#if HAS_TCGEN05
    extern __shared__ char smraw[];
    const unsigned sb_raw = smem_u32(smraw);
    const unsigned pad = (1024u - (sb_raw & 1023u)) & 1023u;
    char* sal = smraw + pad;
    const unsigned sb = sb_raw + pad;          // 1024B-aligned SMEM base

    const int tid = threadIdx.x;
    const int wid = tid >> 5, lid = tid & 31;
    const int row0 = blockIdx.y * 128;
    const int col0 = blockIdx.x * 256;

    if (wid == 0) TCGEN05_ALLOC(sb, 256);
    if (tid == 0) MBARRIER_INIT(sb + 8, 1);
    __syncthreads();
    unsigned tmem;
    asm volatile("ld.shared.b32 %0, [%1];" : "=r"(tmem) : "r"(sb));
    if (wid == 0) TCGEN05_RELINQ();

    // ---- prologue: load K-block 0 into stage 0 ----
    {
        char* tA_hi = sal + 1024;
        char* tA_lo = tA_hi + 16384;
        char* tB_hi = tA_hi + 32768;
        char* tB_lo = tA_hi + 65536;
#pragma unroll
        for (int i = 0; i < 4; i++) {
            int idx = tid + i * 256, r = idx >> 3, c = idx & 7;
            unsigned o = SW128(r * 128 + c * 16);
            *(uint4*)(tA_hi + o) = *(const uint4*)(Ahi + (size_t)(row0 + r) * K + c * 8);
            *(uint4*)(tA_lo + o) = *(const uint4*)(Alo + (size_t)(row0 + r) * K + c * 8);
        }
#pragma unroll
        for (int i = 0; i < 8; i++) {
            int idx = tid + i * 256, r = idx >> 3, c = idx & 7;
            unsigned o = SW128(r * 128 + c * 16);
            *(uint4*)(tB_hi + o) = *(const uint4*)(Bhi + (size_t)(col0 + r) * K + c * 8);
            *(uint4*)(tB_lo + o) = *(const uint4*)(Blo + (size_t)(col0 + r) * K + c * 8);
        }
    }
    FENCE_PROXY_ASYNC();
    __syncthreads();

    const int nkb = K / GKB;   // 16
    for (int t = 0; t < nkb; t++) {
        // 1) issue MMAs for stage t (buffer t&1) + commit -> phase t
        if (wid == 0 && elect_one_pred()) {
            unsigned bufo = sb + 1024 + (unsigned)(t & 1) * GST;
#pragma unroll
            for (int k = 0; k < 4; k++) {
                unsigned long long ka = (unsigned long long)k * 2;  // +32B per K16
#pragma unroll
                for (int h = 0; h < 2; h++) {
                    unsigned d = tmem + h * 128;
                    unsigned long long dAh = make_desc(bufo) + ka;
                    unsigned long long dAl = make_desc(bufo + 16384) + ka;
                    unsigned long long dBh = make_desc(bufo + 32768 + h * 16384) + ka;
                    unsigned long long dBl = make_desc(bufo + 65536 + h * 16384) + ka;
                    mma_ss(d, dAh, dBh, (t == 0 && k == 0) ? 0u : 1u);
                    mma_ss(d, dAh, dBl, 1u);
                    mma_ss(d, dAl, dBh, 1u);
                }
            }
            TCGEN05_COMMIT(sb + 8);
        }

        // 2) global loads for stage t+1 (overlap with MMA t)
        uint4 rAh[4], rAl[4], rBh[8], rBl[8];
        const int kb2 = (t + 1) * GKB;
        if (t + 1 < nkb) {
#pragma unroll
            for (int i = 0; i < 4; i++) {
                int idx = tid + i * 256, r = idx >> 3, c = idx & 7;
                rAh[i] = *(const uint4*)(Ahi + (size_t)(row0 + r) * K + kb2 + c * 8);
                rAl[i] = *(const uint4*)(Alo + (size_t)(row0 + r) * K + kb2 + c * 8);
            }
#pragma unroll
            for (int i = 0; i < 8; i++) {
                int idx = tid + i * 256, r = idx >> 3, c = idx & 7;
                rBh[i] = *(const uint4*)(Bhi + (size_t)(col0 + r) * K + kb2 + c * 8);
                rBl[i] = *(const uint4*)(Blo + (size_t)(col0 + r) * K + kb2 + c * 8);
            }
        }

        // 3) wait for MMA t (phase t, parity t&1) — waits never lag a phase
        MBARRIER_WAIT_PARITY(sb + 8, t & 1);

        // 4) store stage t+1 into buffer (t+1)&1 (MMA t done; buffer free)
        if (t + 1 < nkb) {
            char* st = sal + 1024 + ((t + 1) & 1) * GST;
            char* tA_hi = st;
            char* tA_lo = st + 16384;
            char* tB_hi = st + 32768;
            char* tB_lo = st + 65536;
#pragma unroll
            for (int i = 0; i < 4; i++) {
                int idx = tid + i * 256, r = idx >> 3, c = idx & 7;
                unsigned o = SW128(r * 128 + c * 16);
                *(uint4*)(tA_hi + o) = rAh[i];
                *(uint4*)(tA_lo + o) = rAl[i];
            }
#pragma unroll
            for (int i = 0; i < 8; i++) {
                int idx = tid + i * 256, r = idx >> 3, c = idx & 7;
                unsigned o = SW128(r * 128 + c * 16);
                *(uint4*)(tB_hi + o) = rBh[i];
                *(uint4*)(tB_lo + o) = rBl[i];
            }
        }
        FENCE_PROXY_ASYNC();
        __syncthreads();
    }

    // all phases consumed in-loop; MMA results are complete
    TCGEN05_FENCE_AFTER();

    // epilogue: warps 0-3 read D (256 cols) from TMEM, write C
    if (wid < 4) {
        float* cbase = C + (size_t)(row0 + wid * 32 + lid) * ldC + col0;
#pragma unroll 1
        for (int g = 0; g < 8; g++) {
            unsigned r[32];
            TCGEN05_LD_X32(r, tmem + g * 32);
            TCGEN05_WAIT_LD();
            float* cp = cbase + g * 32;
#pragma unroll
            for (int j = 0; j < 8; j++) {
                float4 o;
                o.x = __uint_as_float(r[4 * j + 0]);
                o.y = __uint_as_float(r[4 * j + 1]);
                o.z = __uint_as_float(r[4 * j + 2]);
                o.w = __uint_as_float(r[4 * j + 3]);
                if (BIAS) {
                    const float4 bb = *(const float4*)&bias[col0 + g * 32 + 4 * j];
                    o.x += bb.x; o.y += bb.y; o.z += bb.z; o.w += bb.w;
                }
                ((float4*)cp)[j] = o;
            }
        }
        TCGEN05_FENCE_BEFORE();
    }

    // Invalidate the mbarrier BEFORE exit: SMEM persists across CTAs on an SM,
    // and mbarrier.init on a still-valid barrier object is UB.
    __syncthreads();
    if (tid == 0) MBARRIER_INVAL(sb + 8);
    __syncthreads();
    if (wid == 0) TCGEN05_DEALLOC(tmem, 256);
#endif  // HAS_TCGEN05
}

// ---------------------------------------------------------------------------
// Split fp32 -> bf16 hi/lo (elementwise, vectorized)
// ---------------------------------------------------------------------------
__global__ __launch_bounds__(256)
void xsplit_kernel(const float* __restrict__ X,
                   __nv_bfloat16* __restrict__ Hi, __nv_bfloat16* __restrict__ Lo)
{
    size_t i = (size_t)blockIdx.x * 256 + threadIdx.x;   // float4 index
    float4 v = ((const float4*)X)[i];
    __nv_bfloat16 h0 = __float2bfloat16(v.x), h1 = __float2bfloat16(v.y);
    __nv_bfloat16 h2 = __float2bfloat16(v.z), h3 = __float2bfloat16(v.w);
    __nv_bfloat162* hp = (__nv_bfloat162*)Hi;
    __nv_bfloat162* lp = (__nv_bfloat162*)Lo;
    hp[2 * i]     = __nv_bfloat162(h0, h1);
    hp[2 * i + 1] = __nv_bfloat162(h2, h3);
    lp[2 * i]     = __nv_bfloat162(__float2bfloat16(v.x - __bfloat162float(h0)),
                                   __float2bfloat16(v.y - __bfloat162float(h1)));
    lp[2 * i + 1] = __nv_bfloat162(__float2bfloat16(v.z - __bfloat162float(h2)),
                                   __float2bfloat16(v.w - __bfloat162float(h3)));
}

// Transpose + split: W[K,N] fp32 -> T_hi/T_lo[N,K] bf16
__global__ __launch_bounds__(256)
void wsplit_kernel(const float* __restrict__ W,
                   __nv_bfloat16* __restrict__ Thi, __nv_bfloat16* __restrict__ Tlo,
                   int K, int N)
{
    __shared__ float tile[32][33];
    int n0 = blockIdx.x * 32, k0 = blockIdx.y * 32;
    int tx = threadIdx.x & 31, ty = threadIdx.x >> 5;   // 32 x 8
#pragma unroll
    for (int r = ty; r < 32; r += 8)
        tile[r][tx] = W[(size_t)(k0 + r) * N + n0 + tx];
    __syncthreads();
#pragma unroll
    for (int r = ty; r < 32; r += 8) {
        float v = tile[tx][r];   // = W[k0+tx][n0+r]
        __nv_bfloat16 h = __float2bfloat16(v);
        Thi[(size_t)(n0 + r) * K + k0 + tx] = h;
        Tlo[(size_t)(n0 + r) * K + k0 + tx] = __float2bfloat16(v - __bfloat162float(h));
    }
}

// ---------------------------------------------------------------------------
// Activation: a = sigmoid(ap + bias), i = sigmoid(ip),
//             s = sqrt(max(1 - a*a, 1e-8)) * (i * v)
// ---------------------------------------------------------------------------
__device__ __forceinline__ float sigmoidf_(float z) {
    return 1.0f / (1.0f + expf(-z));
}

__global__ __launch_bounds__(256)
void act_kernel(const float* __restrict__ aiv, const float* __restrict__ bias,
                float* __restrict__ Aout, float* __restrict__ Sout)
{
    size_t vid = (size_t)blockIdx.x * blockDim.x + threadIdx.x;
    size_t idx = vid * 4;
    size_t r = idx >> 10;
    int d = (int)(idx & 1023);

    const float4 ap = *(const float4*)&aiv[r * N3 + d];
    const float4 ip = *(const float4*)&aiv[r * N3 + 1024 + d];
    const float4 vv = *(const float4*)&aiv[r * N3 + 2048 + d];
    const float4 bb = *(const float4*)&bias[d];

    float4 a4, s4;
    { float a = sigmoidf_(ap.x + bb.x), i = sigmoidf_(ip.x);
      a4.x = a; s4.x = sqrtf(fmaxf(1.0f - a * a, 1e-8f)) * (i * vv.x); }
    { float a = sigmoidf_(ap.y + bb.y), i = sigmoidf_(ip.y);
      a4.y = a; s4.y = sqrtf(fmaxf(1.0f - a * a, 1e-8f)) * (i * vv.y); }
    { float a = sigmoidf_(ap.z + bb.z), i = sigmoidf_(ip.z);
      a4.z = a; s4.z = sqrtf(fmaxf(1.0f - a * a, 1e-8f)) * (i * vv.z); }
    { float a = sigmoidf_(ap.w + bb.w), i = sigmoidf_(ip.w);
      a4.w = a; s4.w = sqrtf(fmaxf(1.0f - a * a, 1e-8f)) * (i * vv.w); }
    *(float4*)&Aout[idx] = a4;
    *(float4*)&Sout[idx] = s4;
}

// ---------------------------------------------------------------------------
// Scan pass A: per-chunk summaries (clamped exactly like the reference)
// ---------------------------------------------------------------------------
__global__ __launch_bounds__(256)
void scan_chunk_kernel(const float* __restrict__ A, const float* __restrict__ S,
                       float* __restrict__ cf, float* __restrict__ cdk)
{
    int d = blockIdx.x * 256 + threadIdx.x;
    int chunk = blockIdx.y;
    int b = blockIdx.z;
    size_t base = ((size_t)(b * SEQ + chunk * CHUNK)) * DREC + d;

    float cl = 0.0f, cw = 0.0f, cd = 1.0f;
#pragma unroll 4
    for (int t = 0; t < CHUNK; t++) {
        float a = A[base + (size_t)t * DREC];
        float s = S[base + (size_t)t * DREC];
        cl += logf(fmaxf(a, 1e-10f));
        cd = expf(cl);
        cw += s / fmaxf(cd, 1e-10f);
    }
    int ci = (b * NCHUNK + chunk) * DREC + d;
    cdk[ci] = cd;
    cf[ci]  = cd * cw;
}

// ---------------------------------------------------------------------------
// Scan pass B: inter-chunk scan, one warp per (b,d), two warp prefix scans.
// ---------------------------------------------------------------------------
__global__ __launch_bounds__(256)
void scan_inter_kernel(const float* __restrict__ cf, const float* __restrict__ cdk,
                       float* __restrict__ inc)
{
    int gw = (blockIdx.x * 256 + threadIdx.x) >> 5;   // 0..4095
    int lane = threadIdx.x & 31;
    int b = gw >> 10, d = gw & 1023;
    size_t base = (size_t)(b * NCHUNK + lane * 4) * DREC + d;

    float ln[4], cf4[4], cl[4];
#pragma unroll
    for (int j = 0; j < 4; j++) {
        ln[j]  = logf(fmaxf(cdk[base + (size_t)j * DREC], 1e-10f));
        cf4[j] = cf[base + (size_t)j * DREC];
    }
    cl[0] = ln[0]; cl[1] = cl[0] + ln[1]; cl[2] = cl[1] + ln[2]; cl[3] = cl[2] + ln[3];
    float tot = cl[3], incl = tot;
#pragma unroll
    for (int o = 1; o < 32; o <<= 1) {
        float v = __shfl_up_sync(0xffffffffu, incl, o);
        if (lane >= o) incl += v;
    }
    float excl = incl - tot;

    float D[4], w[4], W[4];
#pragma unroll
    for (int j = 0; j < 4; j++) {
        cl[j] += excl;
        D[j] = expf(cl[j]);
        w[j] = cf4[j] / fmaxf(D[j], 1e-10f);
    }
    W[0] = w[0]; W[1] = W[0] + w[1]; W[2] = W[1] + w[2]; W[3] = W[2] + w[3];
    float wt = W[3], wincl = wt;
#pragma unroll
    for (int o = 1; o < 32; o <<= 1) {
        float v = __shfl_up_sync(0xffffffffu, wincl, o);
        if (lane >= o) wincl += v;
    }
    float wexcl = wincl - wt;
#pragma unroll
    for (int j = 0; j < 4; j++) W[j] += wexcl;

    float Dp = __shfl_up_sync(0xffffffffu, D[3], 1);
    float Wp = __shfl_up_sync(0xffffffffu, W[3], 1);
    if (lane == 0) { Dp = 1.0f; Wp = 0.0f; }
    inc[base] = Dp * Wp;
#pragma unroll
    for (int j = 1; j < 4; j++)
        inc[base + (size_t)j * DREC] = D[j - 1] * W[j - 1];
}

// ---------------------------------------------------------------------------
// Scan pass C: replay chunk scan + cross contribution, write h as bf16 hi/lo
// ---------------------------------------------------------------------------
__global__ __launch_bounds__(256)
void scan_final_kernel(const float* __restrict__ A, const float* __restrict__ S,
                       const float* __restrict__ inc,
                       __nv_bfloat16* __restrict__ Hhi, __nv_bfloat16* __restrict__ Hlo)
{
    int d = blockIdx.x * 256 + threadIdx.x;
    int chunk = blockIdx.y;
    int b = blockIdx.z;
    size_t base = ((size_t)(b * SEQ + chunk * CHUNK)) * DREC + d;
    float in = inc[(b * NCHUNK + chunk) * DREC + d];

    float cl = 0.0f, cw = 0.0f;
#pragma unroll 4
    for (int t = 0; t < CHUNK; t++) {
        float a = A[base + (size_t)t * DREC];
        float s = S[base + (size_t)t * DREC];
        cl += logf(fmaxf(a, 1e-10f));
        float cd = expf(cl);
        cw += s / fmaxf(cd, 1e-10f);
        float hv = cd * cw + cd * in;
        __nv_bfloat16 hh = __float2bfloat16(hv);
        Hhi[base + (size_t)t * DREC] = hh;
        Hlo[base + (size_t)t * DREC] = __float2bfloat16(hv - __bfloat162float(hh));
    }
}

// ---------------------------------------------------------------------------
// Launch
// ---------------------------------------------------------------------------
extern "C" void kernel_launch(void* const* d_in, const int* in_sizes, int n_in,
                              void* d_out, int out_size)
{
    const float* x      = (const float*)d_in[0];
    const float* W_aiv  = (const float*)d_in[1];
    const float* d_bias = (const float*)d_in[2];
    const float* W_mix  = (const float*)d_in[3];
    const float* b_mix  = (const float*)d_in[4];
    float* out = (float*)d_out;

    float *p_aiv, *p_a, *p_s, *p_cf, *p_cdk, *p_inc;
    __nv_bfloat16 *p_xhi, *p_xlo, *p_hhi, *p_hlo, *p_w1hi, *p_w1lo, *p_w2hi, *p_w2lo;
    cudaGetSymbolAddress((void**)&p_aiv,  g_aiv);
    cudaGetSymbolAddress((void**)&p_a,    g_a);
    cudaGetSymbolAddress((void**)&p_s,    g_s);
    cudaGetSymbolAddress((void**)&p_cf,   g_cf);
    cudaGetSymbolAddress((void**)&p_cdk,  g_cdk);
    cudaGetSymbolAddress((void**)&p_inc,  g_inc);
    cudaGetSymbolAddress((void**)&p_xhi,  g_xhi);
    cudaGetSymbolAddress((void**)&p_xlo,  g_xlo);
    cudaGetSymbolAddress((void**)&p_hhi,  g_hhi);
    cudaGetSymbolAddress((void**)&p_hlo,  g_hlo);
    cudaGetSymbolAddress((void**)&p_w1hi, g_w1hi);
    cudaGetSymbolAddress((void**)&p_w1lo, g_w1lo);
    cudaGetSymbolAddress((void**)&p_w2hi, g_w2hi);
    cudaGetSymbolAddress((void**)&p_w2lo, g_w2lo);

    cudaFuncSetAttribute(gemm_bf16x3_kernel<false>,
                         cudaFuncAttributeMaxDynamicSharedMemorySize, GSMEM);
    cudaFuncSetAttribute(gemm_bf16x3_kernel<true>,
                         cudaFuncAttributeMaxDynamicSharedMemorySize, GSMEM);

    // 0) splits
    xsplit_kernel<<<(MROWS * DMODEL / 4) / 256, 256>>>(x, p_xhi, p_xlo);
    wsplit_kernel<<<dim3(N3 / 32, DMODEL / 32), 256>>>(W_aiv, p_w1hi, p_w1lo, DMODEL, N3);
    wsplit_kernel<<<dim3(DREC / 32, DMODEL / 32), 256>>>(W_mix, p_w2hi, p_w2lo, DMODEL, DREC);

    // 1) aiv = x @ W_aiv  (tcgen05 bf16x3)
    gemm_bf16x3_kernel<false><<<dim3(N3 / 256, MROWS / 128), 256, GSMEM>>>(
        p_xhi, p_xlo, p_w1hi, p_w1lo, nullptr, p_aiv, DMODEL, N3);

    // 2) activations
    act_kernel<<<(MROWS * DREC / 4) / 256, 256>>>(p_aiv, d_bias, p_a, p_s);

    // 3) per-chunk summaries
    scan_chunk_kernel<<<dim3(DREC / 256, NCHUNK, BATCH), 256>>>(p_a, p_s, p_cf, p_cdk);

    // 4) inter-chunk scan (warp-parallel)
    scan_inter_kernel<<<(BATCH * DREC * 32) / 256, 256>>>(p_cf, p_cdk, p_inc);

    // 5) replay + cross contribution -> h (bf16 hi/lo)
    scan_final_kernel<<<dim3(DREC / 256, NCHUNK, BATCH), 256>>>(p_a, p_s, p_inc, p_hhi, p_hlo);

    // 6) out = h @ W_mix + b_mix  (tcgen05 bf16x3)
    gemm_bf16x3_kernel<true><<<dim3(DREC / 256, MROWS / 128), 256, GSMEM>>>(
        p_hhi, p_hlo, p_w2hi, p_w2lo, b_mix, out, DMODEL, DREC);
}

// round 11
// speedup vs baseline: 4.0587x; 1.0059x over previous
#include <cuda_runtime.h>
#include <cuda_bf16.h>
#include <math.h>

// ---------------------------------------------------------------------------
// Arch-specific feature gate: tcgen05 only in the sm_103a ("a") pass; the
// plain compute_103 PTX pass must not see tcgen05 text.
// ---------------------------------------------------------------------------
#ifndef __CUDA_ARCH_HAS_FEATURE__
#define __CUDA_ARCH_HAS_FEATURE__(x) 0
#endif
#if defined(__CUDA_ARCH_FEAT_SM103_ALL) || defined(__CUDA_ARCH_FEAT_SM100_ALL) || \
    defined(__CUDA_ARCH_SPECIFIC__) || __CUDA_ARCH_HAS_FEATURE__(SM103_ALL)
#define HAS_TCGEN05 1
#else
#define HAS_TCGEN05 0
#endif

// Problem constants
#define BATCH   4
#define SEQ     8192
#define DMODEL  1024
#define DREC    1024
#define N3      3072
#define CHUNK   64
#define NCHUNK  128
#define MROWS   (BATCH*SEQ)    // 32768

// ---------------------------------------------------------------------------
// Scratch (allocation-free: __device__ globals)
// ---------------------------------------------------------------------------
__device__ float g_aiv[(size_t)MROWS * N3];              // 402 MB
__device__ float g_a  [(size_t)MROWS * DREC];            // 134 MB
__device__ float g_s  [(size_t)MROWS * DREC];            // 134 MB
__device__ float g_h  [(size_t)MROWS * DREC];            // 134 MB
__device__ __nv_bfloat16 g_w1hi[(size_t)N3 * DMODEL];    // W_aiv^T [N3,K]
__device__ __nv_bfloat16 g_w1lo[(size_t)N3 * DMODEL];
__device__ __nv_bfloat16 g_w2hi[(size_t)DREC * DMODEL];  // W_mix^T [DREC,K]
__device__ __nv_bfloat16 g_w2lo[(size_t)DREC * DMODEL];
__device__ float g_cf [BATCH * NCHUNK * DREC];
__device__ float g_cdk[BATCH * NCHUNK * DREC];
__device__ float g_inc[BATCH * NCHUNK * DREC];

// ---------------------------------------------------------------------------
// Generic helpers (legal on all targets)
// ---------------------------------------------------------------------------
__device__ __forceinline__ unsigned smem_u32(const void* p) {
    unsigned a;
    asm("{ .reg .u64 t; cvta.to.shared.u64 t, %1; cvt.u32.u64 %0, t; }"
        : "=r"(a) : "l"(p));
    return a;
}

#define MBARRIER_INIT(mb, cnt) \
    asm volatile("mbarrier.init.shared.b64 [%0], %1;" \
                 :: "r"((unsigned)(mb)), "r"((unsigned)(cnt)) : "memory")

#define MBARRIER_INVAL(mb) \
    asm volatile("mbarrier.inval.shared.b64 [%0];" \
                 :: "r"((unsigned)(mb)) : "memory")

#define MBARRIER_WAIT_PARITY(mb, par) do { \
    unsigned _mb = (unsigned)(mb), _p = (unsigned)(par), _done; \
    asm volatile("{ .reg .pred p; mbarrier.try_wait.parity.acquire.cta.shared::cta.b64 p, [%1], %2; selp.b32 %0, 1, 0, p; }" \
                 : "=r"(_done) : "r"(_mb), "r"(_p) : "memory"); \
    if (!_done) { \
        asm volatile("{ .reg .pred P1; WL%=: mbarrier.try_wait.parity.acquire.cta.shared::cta.b64 P1, [%0], %1, 0x989680; @P1 bra.uni WD%=; bra.uni WL%=; WD%=: }" \
                     :: "r"(_mb), "r"(_p) : "memory"); \
    } \
} while (0)

#define FENCE_PROXY_ASYNC() asm volatile("fence.proxy.async.shared::cta;" ::: "memory")

// SW128 swizzle on byte offsets within a 1024B-aligned tile
#define SW128(o) ((o) ^ (((o) >> 3) & 0x70))

// fp32 pair -> packed bf16x2 hi + residual lo
__device__ __forceinline__ unsigned pack_hl(float a, float b, unsigned& lo) {
    __nv_bfloat16 ha = __float2bfloat16(a), hb = __float2bfloat16(b);
    __nv_bfloat162 hh(ha, hb);
    __nv_bfloat162 ll(__float2bfloat16(a - __bfloat162float(ha)),
                      __float2bfloat16(b - __bfloat162float(hb)));
    lo = *(unsigned*)&ll;
    return *(unsigned*)&hh;
}

// ---------------------------------------------------------------------------
// tcgen05 helpers — ONLY compiled in the arch-specific pass
// ---------------------------------------------------------------------------
#if HAS_TCGEN05

__device__ __forceinline__ unsigned elect_one_pred() {
    unsigned pred;
    asm volatile("{ .reg .pred p; elect.sync _|p, 0xFFFFFFFF; selp.b32 %0, 1, 0, p; }"
                 : "=r"(pred));
    return pred;
}

#define TCGEN05_ALLOC(sm, n) \
    asm volatile("tcgen05.alloc.cta_group::1.sync.aligned.shared::cta.b32 [%0], %1;" \
                 :: "r"((unsigned)(sm)), "r"((unsigned)(n)) : "memory")
#define TCGEN05_DEALLOC(tm, n) \
    asm volatile("tcgen05.dealloc.cta_group::1.sync.aligned.b32 %0, %1;" \
                 :: "r"(tm), "r"((unsigned)(n)))
#define TCGEN05_RELINQ() \
    asm volatile("tcgen05.relinquish_alloc_permit.cta_group::1.sync.aligned;")
#define TCGEN05_COMMIT(mb) \
    asm volatile("tcgen05.commit.cta_group::1.mbarrier::arrive::one.shared::cluster.b64 [%0];" \
                 :: "r"((unsigned)(mb)) : "memory")
#define TCGEN05_FENCE_AFTER()  asm volatile("tcgen05.fence::after_thread_sync;"  ::: "memory")
#define TCGEN05_FENCE_BEFORE() asm volatile("tcgen05.fence::before_thread_sync;" ::: "memory")
#define TCGEN05_WAIT_LD()      asm volatile("tcgen05.wait::ld.sync.aligned;" ::: "memory")

#define TCGEN05_LD_X32(r, tm) \
    asm volatile("tcgen05.ld.sync.aligned.32x32b.x32.b32 " \
        "{%0, %1, %2, %3, %4, %5, %6, %7, %8, %9, %10, %11, %12, %13, %14, %15, " \
        " %16, %17, %18, %19, %20, %21, %22, %23, %24, %25, %26, %27, %28, %29, %30, %31}, [%32];" \
        : "=r"((r)[0]),  "=r"((r)[1]),  "=r"((r)[2]),  "=r"((r)[3]), \
          "=r"((r)[4]),  "=r"((r)[5]),  "=r"((r)[6]),  "=r"((r)[7]), \
          "=r"((r)[8]),  "=r"((r)[9]),  "=r"((r)[10]), "=r"((r)[11]), \
          "=r"((r)[12]), "=r"((r)[13]), "=r"((r)[14]), "=r"((r)[15]), \
          "=r"((r)[16]), "=r"((r)[17]), "=r"((r)[18]), "=r"((r)[19]), \
          "=r"((r)[20]), "=r"((r)[21]), "=r"((r)[22]), "=r"((r)[23]), \
          "=r"((r)[24]), "=r"((r)[25]), "=r"((r)[26]), "=r"((r)[27]), \
          "=r"((r)[28]), "=r"((r)[29]), "=r"((r)[30]), "=r"((r)[31]) \
        : "r"(tm))

// 64-bit SMEM descriptor: SW128, Blackwell v1, LBO=1, SBO=64
__device__ __forceinline__ unsigned long long make_desc(unsigned addr) {
    const unsigned long long base =
        (2ull << 61) | (1ull << 46) | (64ull << 32) | (1ull << 16);
    return base | ((unsigned long long)(addr >> 4) & 0x3FFF);
}

// cg1 SS bf16 MMA: D[128,128] += A[128,16] * B[128,16]^T, fp32 accum
#define MMA_IDESC 0x8200490u   // F32 out, BF16 A/B, M=128, N=128

__device__ __forceinline__ void mma_ss(unsigned d, unsigned long long a,
                                       unsigned long long b, unsigned acc) {
    asm volatile(
        "{\n\t"
        ".reg .pred p;\n\t"
        "setp.ne.u32 p, %4, 0;\n\t"
        "tcgen05.mma.cta_group::1.kind::f16 [%0], %1, %2, %3, {%5, %5, %5, %5}, p;\n\t"
        "}"
        :: "r"(d), "l"(a), "l"(b), "r"(MMA_IDESC), "r"(acc), "r"(0u)
        : "memory");
}

#endif  // HAS_TCGEN05

// ---------------------------------------------------------------------------
// bf16x3 GEMM: C[M,N] = A_fp32[M,K] @ (Bhi+Blo)[N,K]^T (+ bias)
// A is split to bf16 hi/lo in registers before STS (same global bytes).
// Tile 128(M) x 256(N), K-block 64, 2-stage pipeline with per-stage empty
// mbarriers: MMA(t) overlaps LDG/STS of stage t+1. Waits consume completions
// strictly in order (one outstanding per barrier) -> parity unambiguous.
// ---------------------------------------------------------------------------
#define GKB   64
#define GST   98304   // per-stage: Ahi16K + Alo16K + Bhi32K + Blo32K
#define GSMEM (1024 + 1024 + 2*GST)

template<bool BIAS>
__global__ __launch_bounds__(256, 1)
#if HAS_TCGEN05
__cluster_dims__(1, 1, 1)
#endif
void gemm_bf16x3_kernel(const float* __restrict__ A,
                        const __nv_bfloat16* __restrict__ Bhi,
                        const __nv_bfloat16* __restrict__ Blo,
                        const float* __restrict__ bias,
                        float* __restrict__ C,
                        int K, int ldC)
{
#if HAS_TCGEN05
    extern __shared__ char smraw[];
    const unsigned sb_raw = smem_u32(smraw);
    const unsigned pad = (1024u - (sb_raw & 1023u)) & 1023u;
    char* sal = smraw + pad;
    const unsigned sb = sb_raw + pad;          // 1024B-aligned

    const int tid = threadIdx.x;
    const int wid = tid >> 5, lid = tid & 31;
    const int row0 = blockIdx.y * 128;
    const int col0 = blockIdx.x * 256;

    if (wid == 0) TCGEN05_ALLOC(sb, 256);
    if (tid == 0) { MBARRIER_INIT(sb + 8, 1); MBARRIER_INIT(sb + 16, 1); }
    __syncthreads();
    unsigned tmem;
    asm volatile("ld.shared.b32 %0, [%1];" : "=r"(tmem) : "r"(sb));
    if (wid == 0) TCGEN05_RELINQ();

    unsigned wp0 = 0, wp1 = 0;   // per-barrier wait-parity counters
    const int nkb = K / GKB;     // 16

    for (int t = 0; t < nkb; t++) {
        const int s = t & 1;
        char* buf = sal + 1024 + s * GST;
        const unsigned emp = sb + 8 + 8u * s;
        const int kb = t * GKB;

        // 1) global loads for stage t (overlap with MMA t-1 in flight)
        float4 a0[4], a1[4];
        uint4 bh[8], bl[8];
#pragma unroll
        for (int i = 0; i < 4; i++) {
            int idx = tid + i * 256, r = idx >> 3, c8 = idx & 7;
            const float* ap = A + (size_t)(row0 + r) * K + kb + c8 * 8;
            a0[i] = *(const float4*)ap;
            a1[i] = *(const float4*)(ap + 4);
        }
#pragma unroll
        for (int i = 0; i < 8; i++) {
            int idx = tid + i * 256, r = idx >> 3, c8 = idx & 7;
            bh[i] = *(const uint4*)(Bhi + (size_t)(col0 + r) * K + kb + c8 * 8);
            bl[i] = *(const uint4*)(Blo + (size_t)(col0 + r) * K + kb + c8 * 8);
        }

        // 2) wait for buffer s free (MMA t-2 complete); first two stages free
        if (t >= 2) {
            if (s == 0) { MBARRIER_WAIT_PARITY(emp, wp0); wp0 ^= 1; }
            else        { MBARRIER_WAIT_PARITY(emp, wp1); wp1 ^= 1; }
        }

        // 3) convert A to hi/lo, STS everything (swizzled)
#pragma unroll
        for (int i = 0; i < 4; i++) {
            int idx = tid + i * 256, r = idx >> 3, c8 = idx & 7;
            unsigned o = SW128(r * 128 + c8 * 16);
            uint4 H, L;
            H.x = pack_hl(a0[i].x, a0[i].y, L.x);
            H.y = pack_hl(a0[i].z, a0[i].w, L.y);
            H.z = pack_hl(a1[i].x, a1[i].y, L.z);
            H.w = pack_hl(a1[i].z, a1[i].w, L.w);
            *(uint4*)(buf + o)         = H;
            *(uint4*)(buf + 16384 + o) = L;
        }
#pragma unroll
        for (int i = 0; i < 8; i++) {
            int idx = tid + i * 256, r = idx >> 3, c8 = idx & 7;
            unsigned o = SW128(r * 128 + c8 * 16);
            *(uint4*)(buf + 32768 + o) = bh[i];
            *(uint4*)(buf + 65536 + o) = bl[i];
        }
        FENCE_PROXY_ASYNC();
        __syncthreads();

        // 4) issue MMAs for stage t; commit -> empty[s]
        if (wid == 0 && elect_one_pred()) {
            unsigned bufo = sb + 1024 + (unsigned)s * GST;
#pragma unroll
            for (int k = 0; k < 4; k++) {
                unsigned long long ka = (unsigned long long)k * 2;
#pragma unroll
                for (int h = 0; h < 2; h++) {
                    unsigned d = tmem + h * 128;
                    unsigned long long dAh = make_desc(bufo) + ka;
                    unsigned long long dAl = make_desc(bufo + 16384) + ka;
                    unsigned long long dBh = make_desc(bufo + 32768 + h * 16384) + ka;
                    unsigned long long dBl = make_desc(bufo + 65536 + h * 16384) + ka;
                    mma_ss(d, dAh, dBh, (t == 0 && k == 0) ? 0u : 1u);
                    mma_ss(d, dAh, dBl, 1u);
                    mma_ss(d, dAl, dBh, 1u);
                }
            }
            TCGEN05_COMMIT(emp);
        }
    }

    // drain: consume the final completion of each barrier (in order)
    MBARRIER_WAIT_PARITY(sb + 8,  wp0);
    MBARRIER_WAIT_PARITY(sb + 16, wp1);
    TCGEN05_FENCE_AFTER();

    // epilogue: warps 0-3 read D (256 cols) from TMEM, write C
    if (wid < 4) {
        float* cbase = C + (size_t)(row0 + wid * 32 + lid) * ldC + col0;
#pragma unroll 1
        for (int g = 0; g < 8; g++) {
            unsigned r[32];
            TCGEN05_LD_X32(r, tmem + g * 32);
            TCGEN05_WAIT_LD();
            float* cp = cbase + g * 32;
#pragma unroll
            for (int j = 0; j < 8; j++) {
                float4 o;
                o.x = __uint_as_float(r[4 * j + 0]);
                o.y = __uint_as_float(r[4 * j + 1]);
                o.z = __uint_as_float(r[4 * j + 2]);
                o.w = __uint_as_float(r[4 * j + 3]);
                if (BIAS) {
                    const float4 bb = *(const float4*)&bias[col0 + g * 32 + 4 * j];
                    o.x += bb.x; o.y += bb.y; o.z += bb.z; o.w += bb.w;
                }
                ((float4*)cp)[j] = o;
            }
        }
        TCGEN05_FENCE_BEFORE();
    }

    // inval barriers before exit (SMEM persists across CTAs on an SM)
    __syncthreads();
    if (tid == 0) { MBARRIER_INVAL(sb + 8); MBARRIER_INVAL(sb + 16); }
    __syncthreads();
    if (wid == 0) TCGEN05_DEALLOC(tmem, 256);
#endif  // HAS_TCGEN05
}

// ---------------------------------------------------------------------------
// Transpose + split: W[K,N] fp32 -> T_hi/T_lo[N,K] bf16
// ---------------------------------------------------------------------------
__global__ __launch_bounds__(256)
void wsplit_kernel(const float* __restrict__ W,
                   __nv_bfloat16* __restrict__ Thi, __nv_bfloat16* __restrict__ Tlo,
                   int K, int N)
{
    __shared__ float tile[32][33];
    int n0 = blockIdx.x * 32, k0 = blockIdx.y * 32;
    int tx = threadIdx.x & 31, ty = threadIdx.x >> 5;
#pragma unroll
    for (int r = ty; r < 32; r += 8)
        tile[r][tx] = W[(size_t)(k0 + r) * N + n0 + tx];
    __syncthreads();
#pragma unroll
    for (int r = ty; r < 32; r += 8) {
        float v = tile[tx][r];
        __nv_bfloat16 h = __float2bfloat16(v);
        Thi[(size_t)(n0 + r) * K + k0 + tx] = h;
        Tlo[(size_t)(n0 + r) * K + k0 + tx] = __float2bfloat16(v - __bfloat162float(h));
    }
}

// ---------------------------------------------------------------------------
// Fused activation + per-chunk scan: reads aiv directly, writes a, s, and
// chunk summaries (cf, cdk). Same op order as the reference.
// ---------------------------------------------------------------------------
__device__ __forceinline__ float sigmoidf_(float z) {
    return 1.0f / (1.0f + expf(-z));
}

__global__ __launch_bounds__(256)
void act_scan_kernel(const float* __restrict__ aiv, const float* __restrict__ bias,
                     float* __restrict__ Aout, float* __restrict__ Sout,
                     float* __restrict__ cf, float* __restrict__ cdk)
{
    int d = blockIdx.x * 256 + threadIdx.x;
    int chunk = blockIdx.y;
    int b = blockIdx.z;
    float bb = bias[d];
    size_t row0 = (size_t)(b * SEQ + chunk * CHUNK);

    float cl = 0.0f, cw = 0.0f, cd = 1.0f;
#pragma unroll 4
    for (int t = 0; t < CHUNK; t++) {
        size_t r3 = (row0 + t) * N3;
        float ap = aiv[r3 + d];
        float ip = aiv[r3 + 1024 + d];
        float vv = aiv[r3 + 2048 + d];
        float a = sigmoidf_(ap + bb);
        float i = sigmoidf_(ip);
        float s = sqrtf(fmaxf(1.0f - a * a, 1e-8f)) * (i * vv);
        size_t o = (row0 + t) * DREC + d;
        Aout[o] = a;
        Sout[o] = s;
        cl += logf(fmaxf(a, 1e-10f));
        cd = expf(cl);
        cw += s / fmaxf(cd, 1e-10f);
    }
    int ci = (b * NCHUNK + chunk) * DREC + d;
    cdk[ci] = cd;
    cf[ci]  = cd * cw;
}

// ---------------------------------------------------------------------------
// Inter-chunk scan, one warp per (b,d), two warp prefix scans.
// ---------------------------------------------------------------------------
__global__ __launch_bounds__(256)
void scan_inter_kernel(const float* __restrict__ cf, const float* __restrict__ cdk,
                       float* __restrict__ inc)
{
    int gw = (blockIdx.x * 256 + threadIdx.x) >> 5;
    int lane = threadIdx.x & 31;
    int b = gw >> 10, d = gw & 1023;
    size_t base = (size_t)(b * NCHUNK + lane * 4) * DREC + d;

    float ln[4], cf4[4], cl[4];
#pragma unroll
    for (int j = 0; j < 4; j++) {
        ln[j]  = logf(fmaxf(cdk[base + (size_t)j * DREC], 1e-10f));
        cf4[j] = cf[base + (size_t)j * DREC];
    }
    cl[0] = ln[0]; cl[1] = cl[0] + ln[1]; cl[2] = cl[1] + ln[2]; cl[3] = cl[2] + ln[3];
    float tot = cl[3], incl = tot;
#pragma unroll
    for (int o = 1; o < 32; o <<= 1) {
        float v = __shfl_up_sync(0xffffffffu, incl, o);
        if (lane >= o) incl += v;
    }
    float excl = incl - tot;

    float D[4], w[4], W[4];
#pragma unroll
    for (int j = 0; j < 4; j++) {
        cl[j] += excl;
        D[j] = expf(cl[j]);
        w[j] = cf4[j] / fmaxf(D[j], 1e-10f);
    }
    W[0] = w[0]; W[1] = W[0] + w[1]; W[2] = W[1] + w[2]; W[3] = W[2] + w[3];
    float wt = W[3], wincl = wt;
#pragma unroll
    for (int o = 1; o < 32; o <<= 1) {
        float v = __shfl_up_sync(0xffffffffu, wincl, o);
        if (lane >= o) wincl += v;
    }
    float wexcl = wincl - wt;
#pragma unroll
    for (int j = 0; j < 4; j++) W[j] += wexcl;

    float Dp = __shfl_up_sync(0xffffffffu, D[3], 1);
    float Wp = __shfl_up_sync(0xffffffffu, W[3], 1);
    if (lane == 0) { Dp = 1.0f; Wp = 0.0f; }
    inc[base] = Dp * Wp;
#pragma unroll
    for (int j = 1; j < 4; j++)
        inc[base + (size_t)j * DREC] = D[j - 1] * W[j - 1];
}

// ---------------------------------------------------------------------------
// Replay chunk scan + cross contribution -> h (fp32; GEMM2 splits on the fly)
// ---------------------------------------------------------------------------
__global__ __launch_bounds__(256)
void scan_final_kernel(const float* __restrict__ A, const float* __restrict__ S,
                       const float* __restrict__ inc, float* __restrict__ H)
{
    int d = blockIdx.x * 256 + threadIdx.x;
    int chunk = blockIdx.y;
    int b = blockIdx.z;
    size_t base = ((size_t)(b * SEQ + chunk * CHUNK)) * DREC + d;
    float in = inc[(b * NCHUNK + chunk) * DREC + d];

    float cl = 0.0f, cw = 0.0f;
#pragma unroll 4
    for (int t = 0; t < CHUNK; t++) {
        float a = A[base + (size_t)t * DREC];
        float s = S[base + (size_t)t * DREC];
        cl += logf(fmaxf(a, 1e-10f));
        float cd = expf(cl);
        cw += s / fmaxf(cd, 1e-10f);
        H[base + (size_t)t * DREC] = cd * cw + cd * in;
    }
}

// ---------------------------------------------------------------------------
// Launch
// ---------------------------------------------------------------------------
extern "C" void kernel_launch(void* const* d_in, const int* in_sizes, int n_in,
                              void* d_out, int out_size)
{
    const float* x      = (const float*)d_in[0];
    const float* W_aiv  = (const float*)d_in[1];
    const float* d_bias = (const float*)d_in[2];
    const float* W_mix  = (const float*)d_in[3];
    const float* b_mix  = (const float*)d_in[4];
    float* out = (float*)d_out;

    float *p_aiv, *p_a, *p_s, *p_h, *p_cf, *p_cdk, *p_inc;
    __nv_bfloat16 *p_w1hi, *p_w1lo, *p_w2hi, *p_w2lo;
    cudaGetSymbolAddress((void**)&p_aiv,  g_aiv);
    cudaGetSymbolAddress((void**)&p_a,    g_a);
    cudaGetSymbolAddress((void**)&p_s,    g_s);
    cudaGetSymbolAddress((void**)&p_h,    g_h);
    cudaGetSymbolAddress((void**)&p_cf,   g_cf);
    cudaGetSymbolAddress((void**)&p_cdk,  g_cdk);
    cudaGetSymbolAddress((void**)&p_inc,  g_inc);
    cudaGetSymbolAddress((void**)&p_w1hi, g_w1hi);
    cudaGetSymbolAddress((void**)&p_w1lo, g_w1lo);
    cudaGetSymbolAddress((void**)&p_w2hi, g_w2hi);
    cudaGetSymbolAddress((void**)&p_w2lo, g_w2lo);

    cudaFuncSetAttribute(gemm_bf16x3_kernel<false>,
                         cudaFuncAttributeMaxDynamicSharedMemorySize, GSMEM);
    cudaFuncSetAttribute(gemm_bf16x3_kernel<true>,
                         cudaFuncAttributeMaxDynamicSharedMemorySize, GSMEM);

    // 0) weight splits (transposed)
    wsplit_kernel<<<dim3(N3 / 32, DMODEL / 32), 256>>>(W_aiv, p_w1hi, p_w1lo, DMODEL, N3);
    wsplit_kernel<<<dim3(DREC / 32, DMODEL / 32), 256>>>(W_mix, p_w2hi, p_w2lo, DMODEL, DREC);

    // 1) aiv = x @ W_aiv  (tcgen05 bf16x3; A split in-kernel)
    gemm_bf16x3_kernel<false><<<dim3(N3 / 256, MROWS / 128), 256, GSMEM>>>(
        x, p_w1hi, p_w1lo, nullptr, p_aiv, DMODEL, N3);

    // 2) fused activation + per-chunk scan
    act_scan_kernel<<<dim3(DREC / 256, NCHUNK, BATCH), 256>>>(
        p_aiv, d_bias, p_a, p_s, p_cf, p_cdk);

    // 3) inter-chunk scan (warp-parallel)
    scan_inter_kernel<<<(BATCH * DREC * 32) / 256, 256>>>(p_cf, p_cdk, p_inc);

    // 4) replay + cross contribution -> h (fp32)
    scan_final_kernel<<<dim3(DREC / 256, NCHUNK, BATCH), 256>>>(p_a, p_s, p_inc, p_h);

    // 5) out = h @ W_mix + b_mix
    gemm_bf16x3_kernel<true><<<dim3(DREC / 256, MROWS / 128), 256, GSMEM>>>(
        p_h, p_w2hi, p_w2lo, b_mix, out, DMODEL, DREC);
}

// round 14
// speedup vs baseline: 4.2479x; 1.0466x over previous
#include <cuda_runtime.h>
#include <cuda_bf16.h>
#include <math.h>

// ---------------------------------------------------------------------------
// Arch-specific feature gate: tcgen05 only in the sm_103a ("a") pass.
// ---------------------------------------------------------------------------
#ifndef __CUDA_ARCH_HAS_FEATURE__
#define __CUDA_ARCH_HAS_FEATURE__(x) 0
#endif
#if defined(__CUDA_ARCH_FEAT_SM103_ALL) || defined(__CUDA_ARCH_FEAT_SM100_ALL) || \
    defined(__CUDA_ARCH_SPECIFIC__) || __CUDA_ARCH_HAS_FEATURE__(SM103_ALL)
#define HAS_TCGEN05 1
#else
#define HAS_TCGEN05 0
#endif

// Problem constants
#define BATCH   4
#define SEQ     8192
#define DMODEL  1024
#define DREC    1024
#define N3      3072
#define CHUNK   64
#define NCHUNK  128
#define MROWS   (BATCH*SEQ)    // 32768

// ---------------------------------------------------------------------------
// Scratch (allocation-free: __device__ globals)
// ---------------------------------------------------------------------------
__device__ float g_aiv[(size_t)MROWS * N3];              // 402 MB
__device__ float g_a  [(size_t)MROWS * DREC];            // 134 MB
__device__ float g_s  [(size_t)MROWS * DREC];            // 134 MB
__device__ float g_h  [(size_t)MROWS * DREC];            // 134 MB
__device__ __nv_bfloat16 g_w1hi[(size_t)N3 * DMODEL];    // W_aiv^T [N3,K]
__device__ __nv_bfloat16 g_w1lo[(size_t)N3 * DMODEL];
__device__ __nv_bfloat16 g_w2hi[(size_t)DREC * DMODEL];  // W_mix^T [DREC,K]
__device__ __nv_bfloat16 g_w2lo[(size_t)DREC * DMODEL];
__device__ float g_cf [BATCH * NCHUNK * DREC];
__device__ float g_cdk[BATCH * NCHUNK * DREC];
__device__ float g_inc[BATCH * NCHUNK * DREC];

// ---------------------------------------------------------------------------
// Generic helpers
// ---------------------------------------------------------------------------
__device__ __forceinline__ unsigned smem_u32(const void* p) {
    unsigned a;
    asm("{ .reg .u64 t; cvta.to.shared.u64 t, %1; cvt.u32.u64 %0, t; }"
        : "=r"(a) : "l"(p));
    return a;
}

#define MBARRIER_INIT(mb, cnt) \
    asm volatile("mbarrier.init.shared.b64 [%0], %1;" \
                 :: "r"((unsigned)(mb)), "r"((unsigned)(cnt)) : "memory")

#define MBARRIER_INVAL(mb) \
    asm volatile("mbarrier.inval.shared.b64 [%0];" \
                 :: "r"((unsigned)(mb)) : "memory")

#define MBARRIER_WAIT_PARITY(mb, par) do { \
    unsigned _mb = (unsigned)(mb), _p = (unsigned)(par), _done; \
    asm volatile("{ .reg .pred p; mbarrier.try_wait.parity.acquire.cta.shared::cta.b64 p, [%1], %2; selp.b32 %0, 1, 0, p; }" \
                 : "=r"(_done) : "r"(_mb), "r"(_p) : "memory"); \
    if (!_done) { \
        asm volatile("{ .reg .pred P1; WL%=: mbarrier.try_wait.parity.acquire.cta.shared::cta.b64 P1, [%0], %1, 0x989680; @P1 bra.uni WD%=; bra.uni WL%=; WD%=: }" \
                     :: "r"(_mb), "r"(_p) : "memory"); \
    } \
} while (0)

#define FENCE_PROXY_ASYNC() asm volatile("fence.proxy.async.shared::cta;" ::: "memory")

// SW128 swizzle on byte offsets within a 1024B-aligned tile
#define SW128(o) ((o) ^ (((o) >> 3) & 0x70))

// fp32 pair -> packed bf16x2 hi + residual lo
__device__ __forceinline__ unsigned pack_hl(float a, float b, unsigned& lo) {
    __nv_bfloat16 ha = __float2bfloat16(a), hb = __float2bfloat16(b);
    __nv_bfloat162 hh(ha, hb);
    __nv_bfloat162 ll(__float2bfloat16(a - __bfloat162float(ha)),
                      __float2bfloat16(b - __bfloat162float(hb)));
    lo = *(unsigned*)&ll;
    return *(unsigned*)&hh;
}

// ---------------------------------------------------------------------------
// tcgen05 helpers — ONLY compiled in the arch-specific pass
// ---------------------------------------------------------------------------
#if HAS_TCGEN05

__device__ __forceinline__ unsigned elect_one_pred() {
    unsigned pred;
    asm volatile("{ .reg .pred p; elect.sync _|p, 0xFFFFFFFF; selp.b32 %0, 1, 0, p; }"
                 : "=r"(pred));
    return pred;
}

#define TCGEN05_ALLOC(sm, n) \
    asm volatile("tcgen05.alloc.cta_group::1.sync.aligned.shared::cta.b32 [%0], %1;" \
                 :: "r"((unsigned)(sm)), "r"((unsigned)(n)) : "memory")
#define TCGEN05_DEALLOC(tm, n) \
    asm volatile("tcgen05.dealloc.cta_group::1.sync.aligned.b32 %0, %1;" \
                 :: "r"(tm), "r"((unsigned)(n)))
#define TCGEN05_RELINQ() \
    asm volatile("tcgen05.relinquish_alloc_permit.cta_group::1.sync.aligned;")
#define TCGEN05_COMMIT(mb) \
    asm volatile("tcgen05.commit.cta_group::1.mbarrier::arrive::one.shared::cluster.b64 [%0];" \
                 :: "r"((unsigned)(mb)) : "memory")
#define TCGEN05_FENCE_AFTER()  asm volatile("tcgen05.fence::after_thread_sync;"  ::: "memory")
#define TCGEN05_FENCE_BEFORE() asm volatile("tcgen05.fence::before_thread_sync;" ::: "memory")
#define TCGEN05_WAIT_LD()      asm volatile("tcgen05.wait::ld.sync.aligned;" ::: "memory")

#define TCGEN05_LD_X32(r, tm) \
    asm volatile("tcgen05.ld.sync.aligned.32x32b.x32.b32 " \
        "{%0, %1, %2, %3, %4, %5, %6, %7, %8, %9, %10, %11, %12, %13, %14, %15, " \
        " %16, %17, %18, %19, %20, %21, %22, %23, %24, %25, %26, %27, %28, %29, %30, %31}, [%32];" \
        : "=r"((r)[0]),  "=r"((r)[1]),  "=r"((r)[2]),  "=r"((r)[3]), \
          "=r"((r)[4]),  "=r"((r)[5]),  "=r"((r)[6]),  "=r"((r)[7]), \
          "=r"((r)[8]),  "=r"((r)[9]),  "=r"((r)[10]), "=r"((r)[11]), \
          "=r"((r)[12]), "=r"((r)[13]), "=r"((r)[14]), "=r"((r)[15]), \
          "=r"((r)[16]), "=r"((r)[17]), "=r"((r)[18]), "=r"((r)[19]), \
          "=r"((r)[20]), "=r"((r)[21]), "=r"((r)[22]), "=r"((r)[23]), \
          "=r"((r)[24]), "=r"((r)[25]), "=r"((r)[26]), "=r"((r)[27]), \
          "=r"((r)[28]), "=r"((r)[29]), "=r"((r)[30]), "=r"((r)[31]) \
        : "r"(tm))

// 64-bit SMEM descriptor: SW128, Blackwell v1, LBO=1, SBO=64
__device__ __forceinline__ unsigned long long make_desc(unsigned addr) {
    const unsigned long long base =
        (2ull << 61) | (1ull << 46) | (64ull << 32) | (1ull << 16);
    return base | ((unsigned long long)(addr >> 4) & 0x3FFF);
}

// cg1 SS bf16 MMA: D[128,128] += A[128,16] * B[128,16]^T, fp32 accum
#define MMA_IDESC 0x8200490u   // F32 out, BF16 A/B, M=128, N=128

__device__ __forceinline__ void mma_ss(unsigned d, unsigned long long a,
                                       unsigned long long b, unsigned acc) {
    asm volatile(
        "{\n\t"
        ".reg .pred p;\n\t"
        "setp.ne.u32 p, %4, 0;\n\t"
        "tcgen05.mma.cta_group::1.kind::f16 [%0], %1, %2, %3, {%5, %5, %5, %5}, p;\n\t"
        "}"
        :: "r"(d), "l"(a), "l"(b), "r"(MMA_IDESC), "r"(acc), "r"(0u)
        : "memory");
}

#endif  // HAS_TCGEN05

// ---------------------------------------------------------------------------
// bf16x3 GEMM: C[M,N] = A_fp32[M,K] @ (Bhi+Blo)[N,K]^T (+ bias)
// 512 threads: halves per-thread LDG/convert/STS work (16 warps/SM for
// latency hiding) and splits the TMEM epilogue across two warpgroups.
// Tile 128(M) x 256(N), K-block 64, 2-stage pipeline, per-stage empty
// mbarriers consumed strictly in order (one outstanding per barrier).
// ---------------------------------------------------------------------------
#define GKB   64
#define GST   98304   // per-stage: Ahi16K + Alo16K + Bhi32K + Blo32K
#define GSMEM (1024 + 1024 + 2*GST)
#define GTHREADS 512

template<bool BIAS>
__global__ __launch_bounds__(GTHREADS, 1)
#if HAS_TCGEN05
__cluster_dims__(1, 1, 1)
#endif
void gemm_bf16x3_kernel(const float* __restrict__ A,
                        const __nv_bfloat16* __restrict__ Bhi,
                        const __nv_bfloat16* __restrict__ Blo,
                        const float* __restrict__ bias,
                        float* __restrict__ C,
                        int K, int ldC)
{
#if HAS_TCGEN05
    extern __shared__ char smraw[];
    const unsigned sb_raw = smem_u32(smraw);
    const unsigned pad = (1024u - (sb_raw & 1023u)) & 1023u;
    char* sal = smraw + pad;
    const unsigned sb = sb_raw + pad;          // 1024B-aligned

    const int tid = threadIdx.x;
    const int wid = tid >> 5, lid = tid & 31;
    const int row0 = blockIdx.y * 128;
    const int col0 = blockIdx.x * 256;

    if (wid == 0) TCGEN05_ALLOC(sb, 256);
    if (tid == 0) { MBARRIER_INIT(sb + 8, 1); MBARRIER_INIT(sb + 16, 1); }
    __syncthreads();
    unsigned tmem;
    asm volatile("ld.shared.b32 %0, [%1];" : "=r"(tmem) : "r"(sb));
    if (wid == 0) TCGEN05_RELINQ();

    unsigned wp0 = 0, wp1 = 0;   // per-barrier wait-parity counters
    const int nkb = K / GKB;     // 16

    for (int t = 0; t < nkb; t++) {
        const int s = t & 1;
        char* buf = sal + 1024 + s * GST;
        const unsigned emp = sb + 8 + 8u * s;
        const int kb = t * GKB;

        // 1) global loads for stage t (overlap with MMA t-1 in flight)
        float4 a0[2], a1[2];
        uint4 bh[4], bl[4];
#pragma unroll
        for (int i = 0; i < 2; i++) {
            int idx = tid + i * GTHREADS, r = idx >> 3, c8 = idx & 7;
            const float* ap = A + (size_t)(row0 + r) * K + kb + c8 * 8;
            a0[i] = *(const float4*)ap;
            a1[i] = *(const float4*)(ap + 4);
        }
#pragma unroll
        for (int i = 0; i < 4; i++) {
            int idx = tid + i * GTHREADS, r = idx >> 3, c8 = idx & 7;
            bh[i] = *(const uint4*)(Bhi + (size_t)(col0 + r) * K + kb + c8 * 8);
            bl[i] = *(const uint4*)(Blo + (size_t)(col0 + r) * K + kb + c8 * 8);
        }

        // 2) wait for buffer s free (MMA t-2 complete); first two stages free
        if (t >= 2) {
            if (s == 0) { MBARRIER_WAIT_PARITY(emp, wp0); wp0 ^= 1; }
            else        { MBARRIER_WAIT_PARITY(emp, wp1); wp1 ^= 1; }
        }

        // 3) convert A to hi/lo, STS everything (swizzled)
#pragma unroll
        for (int i = 0; i < 2; i++) {
            int idx = tid + i * GTHREADS, r = idx >> 3, c8 = idx & 7;
            unsigned o = SW128(r * 128 + c8 * 16);
            uint4 H, L;
            H.x = pack_hl(a0[i].x, a0[i].y, L.x);
            H.y = pack_hl(a0[i].z, a0[i].w, L.y);
            H.z = pack_hl(a1[i].x, a1[i].y, L.z);
            H.w = pack_hl(a1[i].z, a1[i].w, L.w);
            *(uint4*)(buf + o)         = H;
            *(uint4*)(buf + 16384 + o) = L;
        }
#pragma unroll
        for (int i = 0; i < 4; i++) {
            int idx = tid + i * GTHREADS, r = idx >> 3, c8 = idx & 7;
            unsigned o = SW128(r * 128 + c8 * 16);
            *(uint4*)(buf + 32768 + o) = bh[i];
            *(uint4*)(buf + 65536 + o) = bl[i];
        }
        FENCE_PROXY_ASYNC();
        __syncthreads();

        // 4) issue MMAs for stage t; commit -> empty[s]
        if (wid == 0 && elect_one_pred()) {
            unsigned bufo = sb + 1024 + (unsigned)s * GST;
#pragma unroll
            for (int k = 0; k < 4; k++) {
                unsigned long long ka = (unsigned long long)k * 2;
#pragma unroll
                for (int h = 0; h < 2; h++) {
                    unsigned d = tmem + h * 128;
                    unsigned long long dAh = make_desc(bufo) + ka;
                    unsigned long long dAl = make_desc(bufo + 16384) + ka;
                    unsigned long long dBh = make_desc(bufo + 32768 + h * 16384) + ka;
                    unsigned long long dBl = make_desc(bufo + 65536 + h * 16384) + ka;
                    mma_ss(d, dAh, dBh, (t == 0 && k == 0) ? 0u : 1u);
                    mma_ss(d, dAh, dBl, 1u);
                    mma_ss(d, dAl, dBh, 1u);
                }
            }
            TCGEN05_COMMIT(emp);
        }
    }

    // drain: consume the final completion of each barrier (in order)
    MBARRIER_WAIT_PARITY(sb + 8,  wp0);
    MBARRIER_WAIT_PARITY(sb + 16, wp1);
    TCGEN05_FENCE_AFTER();

    // epilogue: WG0 -> cols 0-127, WG1 -> cols 128-255
    const int wg = tid >> 7;          // 0..3
    if (wg < 2) {
        const int wiw = (tid >> 5) & 3;   // warp in warpgroup
        float* cbase = C + (size_t)(row0 + wiw * 32 + lid) * ldC + col0 + wg * 128;
        unsigned tbase = tmem + wg * 128;
#pragma unroll 1
        for (int g = 0; g < 4; g++) {
            unsigned r[32];
            TCGEN05_LD_X32(r, tbase + g * 32);
            TCGEN05_WAIT_LD();
            float* cp = cbase + g * 32;
#pragma unroll
            for (int j = 0; j < 8; j++) {
                float4 o;
                o.x = __uint_as_float(r[4 * j + 0]);
                o.y = __uint_as_float(r[4 * j + 1]);
                o.z = __uint_as_float(r[4 * j + 2]);
                o.w = __uint_as_float(r[4 * j + 3]);
                if (BIAS) {
                    const float4 bb = *(const float4*)&bias[col0 + wg * 128 + g * 32 + 4 * j];
                    o.x += bb.x; o.y += bb.y; o.z += bb.z; o.w += bb.w;
                }
                ((float4*)cp)[j] = o;
            }
        }
        TCGEN05_FENCE_BEFORE();
    }

    // inval barriers before exit (SMEM persists across CTAs on an SM)
    __syncthreads();
    if (tid == 0) { MBARRIER_INVAL(sb + 8); MBARRIER_INVAL(sb + 16); }
    __syncthreads();
    if (wid == 0) TCGEN05_DEALLOC(tmem, 256);
#endif  // HAS_TCGEN05
}

// ---------------------------------------------------------------------------
// Transpose + split: W[K,N] fp32 -> T_hi/T_lo[N,K] bf16
// ---------------------------------------------------------------------------
__global__ __launch_bounds__(256)
void wsplit_kernel(const float* __restrict__ W,
                   __nv_bfloat16* __restrict__ Thi, __nv_bfloat16* __restrict__ Tlo,
                   int K, int N)
{
    __shared__ float tile[32][33];
    int n0 = blockIdx.x * 32, k0 = blockIdx.y * 32;
    int tx = threadIdx.x & 31, ty = threadIdx.x >> 5;
#pragma unroll
    for (int r = ty; r < 32; r += 8)
        tile[r][tx] = W[(size_t)(k0 + r) * N + n0 + tx];
    __syncthreads();
#pragma unroll
    for (int r = ty; r < 32; r += 8) {
        float v = tile[tx][r];
        __nv_bfloat16 h = __float2bfloat16(v);
        Thi[(size_t)(n0 + r) * K + k0 + tx] = h;
        Tlo[(size_t)(n0 + r) * K + k0 + tx] = __float2bfloat16(v - __bfloat162float(h));
    }
}

// ---------------------------------------------------------------------------
// Fused activation + per-chunk scan
// ---------------------------------------------------------------------------
__device__ __forceinline__ float sigmoidf_(float z) {
    return 1.0f / (1.0f + expf(-z));
}

__global__ __launch_bounds__(256)
void act_scan_kernel(const float* __restrict__ aiv, const float* __restrict__ bias,
                     float* __restrict__ Aout, float* __restrict__ Sout,
                     float* __restrict__ cf, float* __restrict__ cdk)
{
    int d = blockIdx.x * 256 + threadIdx.x;
    int chunk = blockIdx.y;
    int b = blockIdx.z;
    float bb = bias[d];
    size_t row0 = (size_t)(b * SEQ + chunk * CHUNK);

    float cl = 0.0f, cw = 0.0f, cd = 1.0f;
#pragma unroll 4
    for (int t = 0; t < CHUNK; t++) {
        size_t r3 = (row0 + t) * N3;
        float ap = aiv[r3 + d];
        float ip = aiv[r3 + 1024 + d];
        float vv = aiv[r3 + 2048 + d];
        float a = sigmoidf_(ap + bb);
        float i = sigmoidf_(ip);
        float s = sqrtf(fmaxf(1.0f - a * a, 1e-8f)) * (i * vv);
        size_t o = (row0 + t) * DREC + d;
        Aout[o] = a;
        Sout[o] = s;
        cl += logf(fmaxf(a, 1e-10f));
        cd = expf(cl);
        cw += s / fmaxf(cd, 1e-10f);
    }
    int ci = (b * NCHUNK + chunk) * DREC + d;
    cdk[ci] = cd;
    cf[ci]  = cd * cw;
}

// ---------------------------------------------------------------------------
// Inter-chunk scan, one warp per (b,d)
// ---------------------------------------------------------------------------
__global__ __launch_bounds__(256)
void scan_inter_kernel(const float* __restrict__ cf, const float* __restrict__ cdk,
                       float* __restrict__ inc)
{
    int gw = (blockIdx.x * 256 + threadIdx.x) >> 5;
    int lane = threadIdx.x & 31;
    int b = gw >> 10, d = gw & 1023;
    size_t base = (size_t)(b * NCHUNK + lane * 4) * DREC + d;

    float ln[4], cf4[4], cl[4];
#pragma unroll
    for (int j = 0; j < 4; j++) {
        ln[j]  = logf(fmaxf(cdk[base + (size_t)j * DREC], 1e-10f));
        cf4[j] = cf[base + (size_t)j * DREC];
    }
    cl[0] = ln[0]; cl[1] = cl[0] + ln[1]; cl[2] = cl[1] + ln[2]; cl[3] = cl[2] + ln[3];
    float tot = cl[3], incl = tot;
#pragma unroll
    for (int o = 1; o < 32; o <<= 1) {
        float v = __shfl_up_sync(0xffffffffu, incl, o);
        if (lane >= o) incl += v;
    }
    float excl = incl - tot;

    float D[4], w[4], W[4];
#pragma unroll
    for (int j = 0; j < 4; j++) {
        cl[j] += excl;
        D[j] = expf(cl[j]);
        w[j] = cf4[j] / fmaxf(D[j], 1e-10f);
    }
    W[0] = w[0]; W[1] = W[0] + w[1]; W[2] = W[1] + w[2]; W[3] = W[2] + w[3];
    float wt = W[3], wincl = wt;
#pragma unroll
    for (int o = 1; o < 32; o <<= 1) {
        float v = __shfl_up_sync(0xffffffffu, wincl, o);
        if (lane >= o) wincl += v;
    }
    float wexcl = wincl - wt;
#pragma unroll
    for (int j = 0; j < 4; j++) W[j] += wexcl;

    float Dp = __shfl_up_sync(0xffffffffu, D[3], 1);
    float Wp = __shfl_up_sync(0xffffffffu, W[3], 1);
    if (lane == 0) { Dp = 1.0f; Wp = 0.0f; }
    inc[base] = Dp * Wp;
#pragma unroll
    for (int j = 1; j < 4; j++)
        inc[base + (size_t)j * DREC] = D[j - 1] * W[j - 1];
}

// ---------------------------------------------------------------------------
// Replay chunk scan + cross contribution -> h (fp32; GEMM2 splits on the fly)
// ---------------------------------------------------------------------------
__global__ __launch_bounds__(256)
void scan_final_kernel(const float* __restrict__ A, const float* __restrict__ S,
                       const float* __restrict__ inc, float* __restrict__ H)
{
    int d = blockIdx.x * 256 + threadIdx.x;
    int chunk = blockIdx.y;
    int b = blockIdx.z;
    size_t base = ((size_t)(b * SEQ + chunk * CHUNK)) * DREC + d;
    float in = inc[(b * NCHUNK + chunk) * DREC + d];

    float cl = 0.0f, cw = 0.0f;
#pragma unroll 4
    for (int t = 0; t < CHUNK; t++) {
        float a = A[base + (size_t)t * DREC];
        float s = S[base + (size_t)t * DREC];
        cl += logf(fmaxf(a, 1e-10f));
        float cd = expf(cl);
        cw += s / fmaxf(cd, 1e-10f);
        H[base + (size_t)t * DREC] = cd * cw + cd * in;
    }
}

// ---------------------------------------------------------------------------
// Launch
// ---------------------------------------------------------------------------
extern "C" void kernel_launch(void* const* d_in, const int* in_sizes, int n_in,
                              void* d_out, int out_size)
{
    const float* x      = (const float*)d_in[0];
    const float* W_aiv  = (const float*)d_in[1];
    const float* d_bias = (const float*)d_in[2];
    const float* W_mix  = (const float*)d_in[3];
    const float* b_mix  = (const float*)d_in[4];
    float* out = (float*)d_out;

    float *p_aiv, *p_a, *p_s, *p_h, *p_cf, *p_cdk, *p_inc;
    __nv_bfloat16 *p_w1hi, *p_w1lo, *p_w2hi, *p_w2lo;
    cudaGetSymbolAddress((void**)&p_aiv,  g_aiv);
    cudaGetSymbolAddress((void**)&p_a,    g_a);
    cudaGetSymbolAddress((void**)&p_s,    g_s);
    cudaGetSymbolAddress((void**)&p_h,    g_h);
    cudaGetSymbolAddress((void**)&p_cf,   g_cf);
    cudaGetSymbolAddress((void**)&p_cdk,  g_cdk);
    cudaGetSymbolAddress((void**)&p_inc,  g_inc);
    cudaGetSymbolAddress((void**)&p_w1hi, g_w1hi);
    cudaGetSymbolAddress((void**)&p_w1lo, g_w1lo);
    cudaGetSymbolAddress((void**)&p_w2hi, g_w2hi);
    cudaGetSymbolAddress((void**)&p_w2lo, g_w2lo);

    cudaFuncSetAttribute(gemm_bf16x3_kernel<false>,
                         cudaFuncAttributeMaxDynamicSharedMemorySize, GSMEM);
    cudaFuncSetAttribute(gemm_bf16x3_kernel<true>,
                         cudaFuncAttributeMaxDynamicSharedMemorySize, GSMEM);

    // 0) weight splits (transposed)
    wsplit_kernel<<<dim3(N3 / 32, DMODEL / 32), 256>>>(W_aiv, p_w1hi, p_w1lo, DMODEL, N3);
    wsplit_kernel<<<dim3(DREC / 32, DMODEL / 32), 256>>>(W_mix, p_w2hi, p_w2lo, DMODEL, DREC);

    // 1) aiv = x @ W_aiv  (tcgen05 bf16x3; A split in-kernel)
    gemm_bf16x3_kernel<false><<<dim3(N3 / 256, MROWS / 128), GTHREADS, GSMEM>>>(
        x, p_w1hi, p_w1lo, nullptr, p_aiv, DMODEL, N3);

    // 2) fused activation + per-chunk scan
    act_scan_kernel<<<dim3(DREC / 256, NCHUNK, BATCH), 256>>>(
        p_aiv, d_bias, p_a, p_s, p_cf, p_cdk);

    // 3) inter-chunk scan (warp-parallel)
    scan_inter_kernel<<<(BATCH * DREC * 32) / 256, 256>>>(p_cf, p_cdk, p_inc);

    // 4) replay + cross contribution -> h (fp32)
    scan_final_kernel<<<dim3(DREC / 256, NCHUNK, BATCH), 256>>>(p_a, p_s, p_inc, p_h);

    // 5) out = h @ W_mix + b_mix
    gemm_bf16x3_kernel<true><<<dim3(DREC / 256, MROWS / 128), GTHREADS, GSMEM>>>(
        p_h, p_w2hi, p_w2lo, b_mix, out, DMODEL, DREC);
}

// round 15
// speedup vs baseline: 4.8148x; 1.1334x over previous
#include <cuda_runtime.h>
#include <cuda_bf16.h>
#include <math.h>

// ---------------------------------------------------------------------------
// Arch-specific feature gate: tcgen05 only in the sm_103a ("a") pass.
// ---------------------------------------------------------------------------
#ifndef __CUDA_ARCH_HAS_FEATURE__
#define __CUDA_ARCH_HAS_FEATURE__(x) 0
#endif
#if defined(__CUDA_ARCH_FEAT_SM103_ALL) || defined(__CUDA_ARCH_FEAT_SM100_ALL) || \
    defined(__CUDA_ARCH_SPECIFIC__) || __CUDA_ARCH_HAS_FEATURE__(SM103_ALL)
#define HAS_TCGEN05 1
#else
#define HAS_TCGEN05 0
#endif

// Problem constants
#define BATCH   4
#define SEQ     8192
#define DMODEL  1024
#define DREC    1024
#define N3      3072
#define CHUNK   64
#define NCHUNK  128
#define MROWS   (BATCH*SEQ)    // 32768

// ---------------------------------------------------------------------------
// Scratch (allocation-free: __device__ globals)
// ---------------------------------------------------------------------------
__device__ float g_aiv[(size_t)MROWS * N3];              // 402 MB
__device__ float g_a  [(size_t)MROWS * DREC];            // 134 MB
__device__ float g_s  [(size_t)MROWS * DREC];            // 134 MB
__device__ float g_h  [(size_t)MROWS * DREC];            // 134 MB
__device__ __nv_bfloat16 g_w1hi[(size_t)N3 * DMODEL];    // W_aiv^T [N3,K]
__device__ __nv_bfloat16 g_w1lo[(size_t)N3 * DMODEL];
__device__ __nv_bfloat16 g_w2hi[(size_t)DREC * DMODEL];  // W_mix^T [DREC,K]
__device__ __nv_bfloat16 g_w2lo[(size_t)DREC * DMODEL];
__device__ float g_cf [BATCH * NCHUNK * DREC];
__device__ float g_cdk[BATCH * NCHUNK * DREC];
__device__ float g_inc[BATCH * NCHUNK * DREC];

// ---------------------------------------------------------------------------
// Generic helpers
// ---------------------------------------------------------------------------
__device__ __forceinline__ unsigned smem_u32(const void* p) {
    unsigned a;
    asm("{ .reg .u64 t; cvta.to.shared.u64 t, %1; cvt.u32.u64 %0, t; }"
        : "=r"(a) : "l"(p));
    return a;
}

#define MBARRIER_INIT(mb, cnt) \
    asm volatile("mbarrier.init.shared.b64 [%0], %1;" \
                 :: "r"((unsigned)(mb)), "r"((unsigned)(cnt)) : "memory")

#define MBARRIER_INVAL(mb) \
    asm volatile("mbarrier.inval.shared.b64 [%0];" \
                 :: "r"((unsigned)(mb)) : "memory")

#define MBARRIER_WAIT_PARITY(mb, par) do { \
    unsigned _mb = (unsigned)(mb), _p = (unsigned)(par), _done; \
    asm volatile("{ .reg .pred p; mbarrier.try_wait.parity.acquire.cta.shared::cta.b64 p, [%1], %2; selp.b32 %0, 1, 0, p; }" \
                 : "=r"(_done) : "r"(_mb), "r"(_p) : "memory"); \
    if (!_done) { \
        asm volatile("{ .reg .pred P1; WL%=: mbarrier.try_wait.parity.acquire.cta.shared::cta.b64 P1, [%0], %1, 0x989680; @P1 bra.uni WD%=; bra.uni WL%=; WD%=: }" \
                     :: "r"(_mb), "r"(_p) : "memory"); \
    } \
} while (0)

#define FENCE_PROXY_ASYNC() asm volatile("fence.proxy.async.shared::cta;" ::: "memory")

// cp.async (sm_80+; legal in both compilation passes)
#define CP_ASYNC_CG(dst_u32, src_ptr) \
    asm volatile("cp.async.cg.shared.global [%0], [%1], 16;" \
                 :: "r"((unsigned)(dst_u32)), "l"(src_ptr) : "memory")
#define CP_ASYNC_COMMIT() asm volatile("cp.async.commit_group;" ::: "memory")
#define CP_ASYNC_WAIT0()  asm volatile("cp.async.wait_group 0;" ::: "memory")

// SW128 swizzle on byte offsets within a 1024B-aligned tile
#define SW128(o) ((o) ^ (((o) >> 3) & 0x70))

// fp32 pair -> packed bf16x2 hi + residual lo
__device__ __forceinline__ unsigned pack_hl(float a, float b, unsigned& lo) {
    __nv_bfloat16 ha = __float2bfloat16(a), hb = __float2bfloat16(b);
    __nv_bfloat162 hh(ha, hb);
    __nv_bfloat162 ll(__float2bfloat16(a - __bfloat162float(ha)),
                      __float2bfloat16(b - __bfloat162float(hb)));
    lo = *(unsigned*)&ll;
    return *(unsigned*)&hh;
}

// ---------------------------------------------------------------------------
// tcgen05 helpers — ONLY compiled in the arch-specific pass
// ---------------------------------------------------------------------------
#if HAS_TCGEN05

__device__ __forceinline__ unsigned elect_one_pred() {
    unsigned pred;
    asm volatile("{ .reg .pred p; elect.sync _|p, 0xFFFFFFFF; selp.b32 %0, 1, 0, p; }"
                 : "=r"(pred));
    return pred;
}

#define TCGEN05_ALLOC(sm, n) \
    asm volatile("tcgen05.alloc.cta_group::1.sync.aligned.shared::cta.b32 [%0], %1;" \
                 :: "r"((unsigned)(sm)), "r"((unsigned)(n)) : "memory")
#define TCGEN05_DEALLOC(tm, n) \
    asm volatile("tcgen05.dealloc.cta_group::1.sync.aligned.b32 %0, %1;" \
                 :: "r"(tm), "r"((unsigned)(n)))
#define TCGEN05_RELINQ() \
    asm volatile("tcgen05.relinquish_alloc_permit.cta_group::1.sync.aligned;")
#define TCGEN05_COMMIT(mb) \
    asm volatile("tcgen05.commit.cta_group::1.mbarrier::arrive::one.shared::cluster.b64 [%0];" \
                 :: "r"((unsigned)(mb)) : "memory")
#define TCGEN05_FENCE_AFTER()  asm volatile("tcgen05.fence::after_thread_sync;"  ::: "memory")
#define TCGEN05_FENCE_BEFORE() asm volatile("tcgen05.fence::before_thread_sync;" ::: "memory")
#define TCGEN05_WAIT_LD()      asm volatile("tcgen05.wait::ld.sync.aligned;" ::: "memory")

#define TCGEN05_LD_X32(r, tm) \
    asm volatile("tcgen05.ld.sync.aligned.32x32b.x32.b32 " \
        "{%0, %1, %2, %3, %4, %5, %6, %7, %8, %9, %10, %11, %12, %13, %14, %15, " \
        " %16, %17, %18, %19, %20, %21, %22, %23, %24, %25, %26, %27, %28, %29, %30, %31}, [%32];" \
        : "=r"((r)[0]),  "=r"((r)[1]),  "=r"((r)[2]),  "=r"((r)[3]), \
          "=r"((r)[4]),  "=r"((r)[5]),  "=r"((r)[6]),  "=r"((r)[7]), \
          "=r"((r)[8]),  "=r"((r)[9]),  "=r"((r)[10]), "=r"((r)[11]), \
          "=r"((r)[12]), "=r"((r)[13]), "=r"((r)[14]), "=r"((r)[15]), \
          "=r"((r)[16]), "=r"((r)[17]), "=r"((r)[18]), "=r"((r)[19]), \
          "=r"((r)[20]), "=r"((r)[21]), "=r"((r)[22]), "=r"((r)[23]), \
          "=r"((r)[24]), "=r"((r)[25]), "=r"((r)[26]), "=r"((r)[27]), \
          "=r"((r)[28]), "=r"((r)[29]), "=r"((r)[30]), "=r"((r)[31]) \
        : "r"(tm))

// 64-bit SMEM descriptor: SW128, Blackwell v1, LBO=1, SBO=64
__device__ __forceinline__ unsigned long long make_desc(unsigned addr) {
    const unsigned long long base =
        (2ull << 61) | (1ull << 46) | (64ull << 32) | (1ull << 16);
    return base | ((unsigned long long)(addr >> 4) & 0x3FFF);
}

// cg1 SS bf16 MMA: D[128,128] += A[128,16] * B[128,16]^T, fp32 accum
#define MMA_IDESC 0x8200490u   // F32 out, BF16 A/B, M=128, N=128

__device__ __forceinline__ void mma_ss(unsigned d, unsigned long long a,
                                       unsigned long long b, unsigned acc) {
    asm volatile(
        "{\n\t"
        ".reg .pred p;\n\t"
        "setp.ne.u32 p, %4, 0;\n\t"
        "tcgen05.mma.cta_group::1.kind::f16 [%0], %1, %2, %3, {%5, %5, %5, %5}, p;\n\t"
        "}"
        :: "r"(d), "l"(a), "l"(b), "r"(MMA_IDESC), "r"(acc), "r"(0u)
        : "memory");
}

#endif  // HAS_TCGEN05

// ---------------------------------------------------------------------------
// bf16x3 GEMM: C[M,N] = A_fp32[M,K] @ (Bhi+Blo)[N,K]^T (+ bias)
// 512 threads. B operands move L2->SMEM via cp.async.cg (no registers, L1
// bypass); A is loaded fp32, split hi/lo in registers, STS'd. Loop order:
// LDG A(t+1) -> MMA(t)+commit -> wait empty[(t+1)&1] (MMA t-1; in-order
// parity) -> cp.async B(t+1) + STS A(t+1) -> wait_group 0 -> fence+sync,
// so the MMA overlaps all of stage t+1's data movement.
// ---------------------------------------------------------------------------
#define GKB   64
#define GST   98304   // per-stage: Ahi16K + Alo16K + Bhi32K + Blo32K
#define GSMEM (1024 + 1024 + 2*GST)
#define GTHREADS 512

template<bool BIAS>
__global__ __launch_bounds__(GTHREADS, 1)
#if HAS_TCGEN05
__cluster_dims__(1, 1, 1)
#endif
void gemm_bf16x3_kernel(const float* __restrict__ A,
                        const __nv_bfloat16* __restrict__ Bhi,
                        const __nv_bfloat16* __restrict__ Blo,
                        const float* __restrict__ bias,
                        float* __restrict__ C,
                        int K, int ldC)
{
#if HAS_TCGEN05
    extern __shared__ char smraw[];
    const unsigned sb_raw = smem_u32(smraw);
    const unsigned pad = (1024u - (sb_raw & 1023u)) & 1023u;
    char* sal = smraw + pad;
    const unsigned sb = sb_raw + pad;          // 1024B-aligned

    const int tid = threadIdx.x;
    const int wid = tid >> 5, lid = tid & 31;
    const int row0 = blockIdx.y * 128;
    const int col0 = blockIdx.x * 256;

    if (wid == 0) TCGEN05_ALLOC(sb, 256);
    if (tid == 0) { MBARRIER_INIT(sb + 8, 1); MBARRIER_INIT(sb + 16, 1); }
    __syncthreads();
    unsigned tmem;
    asm volatile("ld.shared.b32 %0, [%1];" : "=r"(tmem) : "r"(sb));
    if (wid == 0) TCGEN05_RELINQ();

    // per-thread tile coordinates
    const int rA = (tid + 0 * GTHREADS) >> 3;           // A row pattern base
    unsigned wp0 = 0, wp1 = 0;
    const int nkb = K / GKB;     // 16
    (void)rA;

    // ---- prologue: fill stage 0 ----
    {
        const unsigned bufo = sb + 1024;
        char* buf = sal + 1024;
        // B via cp.async (hi + lo)
#pragma unroll
        for (int i = 0; i < 4; i++) {
            int idx = tid + i * GTHREADS, r = idx >> 3, c8 = idx & 7;
            unsigned o = SW128(r * 128 + c8 * 16);
            CP_ASYNC_CG(bufo + 32768 + o, Bhi + (size_t)(col0 + r) * K + c8 * 8);
            CP_ASYNC_CG(bufo + 65536 + o, Blo + (size_t)(col0 + r) * K + c8 * 8);
        }
        CP_ASYNC_COMMIT();
        // A manual: load fp32, split, STS
#pragma unroll
        for (int i = 0; i < 2; i++) {
            int idx = tid + i * GTHREADS, r = idx >> 3, c8 = idx & 7;
            const float* ap = A + (size_t)(row0 + r) * K + c8 * 8;
            float4 x0 = *(const float4*)ap;
            float4 x1 = *(const float4*)(ap + 4);
            unsigned o = SW128(r * 128 + c8 * 16);
            uint4 H, L;
            H.x = pack_hl(x0.x, x0.y, L.x);
            H.y = pack_hl(x0.z, x0.w, L.y);
            H.z = pack_hl(x1.x, x1.y, L.z);
            H.w = pack_hl(x1.z, x1.w, L.w);
            *(uint4*)(buf + o)         = H;
            *(uint4*)(buf + 16384 + o) = L;
        }
        CP_ASYNC_WAIT0();
        FENCE_PROXY_ASYNC();
        __syncthreads();
    }

    for (int t = 0; t < nkb; t++) {
        const int s = t & 1;
        const int s2 = s ^ 1;
        const int kb2 = (t + 1) * GKB;

        // 1) A loads for stage t+1 (long-latency first)
        float4 x0[2], x1[2];
        if (t + 1 < nkb) {
#pragma unroll
            for (int i = 0; i < 2; i++) {
                int idx = tid + i * GTHREADS, r = idx >> 3, c8 = idx & 7;
                const float* ap = A + (size_t)(row0 + r) * K + kb2 + c8 * 8;
                x0[i] = *(const float4*)ap;
                x1[i] = *(const float4*)(ap + 4);
            }
        }

        // 2) issue MMAs for stage t (buf s); commit -> empty[s]
        if (wid == 0 && elect_one_pred()) {
            unsigned bufo = sb + 1024 + (unsigned)s * GST;
#pragma unroll
            for (int k = 0; k < 4; k++) {
                unsigned long long ka = (unsigned long long)k * 2;
#pragma unroll
                for (int h = 0; h < 2; h++) {
                    unsigned d = tmem + h * 128;
                    unsigned long long dAh = make_desc(bufo) + ka;
                    unsigned long long dAl = make_desc(bufo + 16384) + ka;
                    unsigned long long dBh = make_desc(bufo + 32768 + h * 16384) + ka;
                    unsigned long long dBl = make_desc(bufo + 65536 + h * 16384) + ka;
                    mma_ss(d, dAh, dBh, (t == 0 && k == 0) ? 0u : 1u);
                    mma_ss(d, dAh, dBl, 1u);
                    mma_ss(d, dAl, dBh, 1u);
                }
            }
            TCGEN05_COMMIT(sb + 8 + 8u * s);
        }

        // 3) fill stage t+1 into buf s2 (overlapped with MMA t)
        if (t + 1 < nkb) {
            // buffer s2 free once MMA(t-1) completed
            if (t >= 1) {
                const unsigned emp2 = sb + 8 + 8u * s2;
                if (s2 == 0) { MBARRIER_WAIT_PARITY(emp2, wp0); wp0 ^= 1; }
                else         { MBARRIER_WAIT_PARITY(emp2, wp1); wp1 ^= 1; }
            }
            const unsigned bufo2 = sb + 1024 + (unsigned)s2 * GST;
            char* buf2 = sal + 1024 + s2 * GST;
            // B via cp.async
#pragma unroll
            for (int i = 0; i < 4; i++) {
                int idx = tid + i * GTHREADS, r = idx >> 3, c8 = idx & 7;
                unsigned o = SW128(r * 128 + c8 * 16);
                CP_ASYNC_CG(bufo2 + 32768 + o, Bhi + (size_t)(col0 + r) * K + kb2 + c8 * 8);
                CP_ASYNC_CG(bufo2 + 65536 + o, Blo + (size_t)(col0 + r) * K + kb2 + c8 * 8);
            }
            CP_ASYNC_COMMIT();
            // A convert + STS
#pragma unroll
            for (int i = 0; i < 2; i++) {
                int idx = tid + i * GTHREADS, r = idx >> 3, c8 = idx & 7;
                unsigned o = SW128(r * 128 + c8 * 16);
                uint4 H, L;
                H.x = pack_hl(x0[i].x, x0[i].y, L.x);
                H.y = pack_hl(x0[i].z, x0[i].w, L.y);
                H.z = pack_hl(x1[i].x, x1[i].y, L.z);
                H.w = pack_hl(x1[i].z, x1[i].w, L.w);
                *(uint4*)(buf2 + o)         = H;
                *(uint4*)(buf2 + 16384 + o) = L;
            }
            CP_ASYNC_WAIT0();
            FENCE_PROXY_ASYNC();
            __syncthreads();
        }
    }

    // drain: last MMA's commit is on barrier (nkb-1)&1; the other barrier's
    // commits were all consumed in-loop.
    {
        const int lb = (nkb - 1) & 1;
        const unsigned emp = sb + 8 + 8u * lb;
        if (lb == 0) MBARRIER_WAIT_PARITY(emp, wp0);
        else         MBARRIER_WAIT_PARITY(emp, wp1);
    }
    TCGEN05_FENCE_AFTER();

    // epilogue: WG0 -> cols 0-127, WG1 -> cols 128-255
    const int wg = tid >> 7;          // 0..3
    if (wg < 2) {
        const int wiw = (tid >> 5) & 3;
        float* cbase = C + (size_t)(row0 + wiw * 32 + lid) * ldC + col0 + wg * 128;
        unsigned tbase = tmem + wg * 128;
#pragma unroll 1
        for (int g = 0; g < 4; g++) {
            unsigned r[32];
            TCGEN05_LD_X32(r, tbase + g * 32);
            TCGEN05_WAIT_LD();
            float* cp = cbase + g * 32;
#pragma unroll
            for (int j = 0; j < 8; j++) {
                float4 o;
                o.x = __uint_as_float(r[4 * j + 0]);
                o.y = __uint_as_float(r[4 * j + 1]);
                o.z = __uint_as_float(r[4 * j + 2]);
                o.w = __uint_as_float(r[4 * j + 3]);
                if (BIAS) {
                    const float4 bb = *(const float4*)&bias[col0 + wg * 128 + g * 32 + 4 * j];
                    o.x += bb.x; o.y += bb.y; o.z += bb.z; o.w += bb.w;
                }
                ((float4*)cp)[j] = o;
            }
        }
        TCGEN05_FENCE_BEFORE();
    }

    // inval barriers before exit (SMEM persists across CTAs on an SM)
    __syncthreads();
    if (tid == 0) { MBARRIER_INVAL(sb + 8); MBARRIER_INVAL(sb + 16); }
    __syncthreads();
    if (wid == 0) TCGEN05_DEALLOC(tmem, 256);
#endif  // HAS_TCGEN05
}

// ---------------------------------------------------------------------------
// Transpose + split: W[K,N] fp32 -> T_hi/T_lo[N,K] bf16
// ---------------------------------------------------------------------------
__global__ __launch_bounds__(256)
void wsplit_kernel(const float* __restrict__ W,
                   __nv_bfloat16* __restrict__ Thi, __nv_bfloat16* __restrict__ Tlo,
                   int K, int N)
{
    __shared__ float tile[32][33];
    int n0 = blockIdx.x * 32, k0 = blockIdx.y * 32;
    int tx = threadIdx.x & 31, ty = threadIdx.x >> 5;
#pragma unroll
    for (int r = ty; r < 32; r += 8)
        tile[r][tx] = W[(size_t)(k0 + r) * N + n0 + tx];
    __syncthreads();
#pragma unroll
    for (int r = ty; r < 32; r += 8) {
        float v = tile[tx][r];
        __nv_bfloat16 h = __float2bfloat16(v);
        Thi[(size_t)(n0 + r) * K + k0 + tx] = h;
        Tlo[(size_t)(n0 + r) * K + k0 + tx] = __float2bfloat16(v - __bfloat162float(h));
    }
}

// ---------------------------------------------------------------------------
// Fused activation + per-chunk scan
// ---------------------------------------------------------------------------
__device__ __forceinline__ float sigmoidf_(float z) {
    return 1.0f / (1.0f + expf(-z));
}

__global__ __launch_bounds__(256)
void act_scan_kernel(const float* __restrict__ aiv, const float* __restrict__ bias,
                     float* __restrict__ Aout, float* __restrict__ Sout,
                     float* __restrict__ cf, float* __restrict__ cdk)
{
    int d = blockIdx.x * 256 + threadIdx.x;
    int chunk = blockIdx.y;
    int b = blockIdx.z;
    float bb = bias[d];
    size_t row0 = (size_t)(b * SEQ + chunk * CHUNK);

    float cl = 0.0f, cw = 0.0f, cd = 1.0f;
#pragma unroll 4
    for (int t = 0; t < CHUNK; t++) {
        size_t r3 = (row0 + t) * N3;
        float ap = aiv[r3 + d];
        float ip = aiv[r3 + 1024 + d];
        float vv = aiv[r3 + 2048 + d];
        float a = sigmoidf_(ap + bb);
        float i = sigmoidf_(ip);
        float s = sqrtf(fmaxf(1.0f - a * a, 1e-8f)) * (i * vv);
        size_t o = (row0 + t) * DREC + d;
        Aout[o] = a;
        Sout[o] = s;
        cl += logf(fmaxf(a, 1e-10f));
        cd = expf(cl);
        cw += s / fmaxf(cd, 1e-10f);
    }
    int ci = (b * NCHUNK + chunk) * DREC + d;
    cdk[ci] = cd;
    cf[ci]  = cd * cw;
}

// ---------------------------------------------------------------------------
// Inter-chunk scan, one warp per (b,d)
// ---------------------------------------------------------------------------
__global__ __launch_bounds__(256)
void scan_inter_kernel(const float* __restrict__ cf, const float* __restrict__ cdk,
                       float* __restrict__ inc)
{
    int gw = (blockIdx.x * 256 + threadIdx.x) >> 5;
    int lane = threadIdx.x & 31;
    int b = gw >> 10, d = gw & 1023;
    size_t base = (size_t)(b * NCHUNK + lane * 4) * DREC + d;

    float ln[4], cf4[4], cl[4];
#pragma unroll
    for (int j = 0; j < 4; j++) {
        ln[j]  = logf(fmaxf(cdk[base + (size_t)j * DREC], 1e-10f));
        cf4[j] = cf[base + (size_t)j * DREC];
    }
    cl[0] = ln[0]; cl[1] = cl[0] + ln[1]; cl[2] = cl[1] + ln[2]; cl[3] = cl[2] + ln[3];
    float tot = cl[3], incl = tot;
#pragma unroll
    for (int o = 1; o < 32; o <<= 1) {
        float v = __shfl_up_sync(0xffffffffu, incl, o);
        if (lane >= o) incl += v;
    }
    float excl = incl - tot;

    float D[4], w[4], W[4];
#pragma unroll
    for (int j = 0; j < 4; j++) {
        cl[j] += excl;
        D[j] = expf(cl[j]);
        w[j] = cf4[j] / fmaxf(D[j], 1e-10f);
    }
    W[0] = w[0]; W[1] = W[0] + w[1]; W[2] = W[1] + w[2]; W[3] = W[2] + w[3];
    float wt = W[3], wincl = wt;
#pragma unroll
    for (int o = 1; o < 32; o <<= 1) {
        float v = __shfl_up_sync(0xffffffffu, wincl, o);
        if (lane >= o) wincl += v;
    }
    float wexcl = wincl - wt;
#pragma unroll
    for (int j = 0; j < 4; j++) W[j] += wexcl;

    float Dp = __shfl_up_sync(0xffffffffu, D[3], 1);
    float Wp = __shfl_up_sync(0xffffffffu, W[3], 1);
    if (lane == 0) { Dp = 1.0f; Wp = 0.0f; }
    inc[base] = Dp * Wp;
#pragma unroll
    for (int j = 1; j < 4; j++)
        inc[base + (size_t)j * DREC] = D[j - 1] * W[j - 1];
}

// ---------------------------------------------------------------------------
// Replay chunk scan + cross contribution -> h (fp32)
// ---------------------------------------------------------------------------
__global__ __launch_bounds__(256)
void scan_final_kernel(const float* __restrict__ A, const float* __restrict__ S,
                       const float* __restrict__ inc, float* __restrict__ H)
{
    int d = blockIdx.x * 256 + threadIdx.x;
    int chunk = blockIdx.y;
    int b = blockIdx.z;
    size_t base = ((size_t)(b * SEQ + chunk * CHUNK)) * DREC + d;
    float in = inc[(b * NCHUNK + chunk) * DREC + d];

    float cl = 0.0f, cw = 0.0f;
#pragma unroll 4
    for (int t = 0; t < CHUNK; t++) {
        float a = A[base + (size_t)t * DREC];
        float s = S[base + (size_t)t * DREC];
        cl += logf(fmaxf(a, 1e-10f));
        float cd = expf(cl);
        cw += s / fmaxf(cd, 1e-10f);
        H[base + (size_t)t * DREC] = cd * cw + cd * in;
    }
}

// ---------------------------------------------------------------------------
// Launch
// ---------------------------------------------------------------------------
extern "C" void kernel_launch(void* const* d_in, const int* in_sizes, int n_in,
                              void* d_out, int out_size)
{
    const float* x      = (const float*)d_in[0];
    const float* W_aiv  = (const float*)d_in[1];
    const float* d_bias = (const float*)d_in[2];
    const float* W_mix  = (const float*)d_in[3];
    const float* b_mix  = (const float*)d_in[4];
    float* out = (float*)d_out;

    float *p_aiv, *p_a, *p_s, *p_h, *p_cf, *p_cdk, *p_inc;
    __nv_bfloat16 *p_w1hi, *p_w1lo, *p_w2hi, *p_w2lo;
    cudaGetSymbolAddress((void**)&p_aiv,  g_aiv);
    cudaGetSymbolAddress((void**)&p_a,    g_a);
    cudaGetSymbolAddress((void**)&p_s,    g_s);
    cudaGetSymbolAddress((void**)&p_h,    g_h);
    cudaGetSymbolAddress((void**)&p_cf,   g_cf);
    cudaGetSymbolAddress((void**)&p_cdk,  g_cdk);
    cudaGetSymbolAddress((void**)&p_inc,  g_inc);
    cudaGetSymbolAddress((void**)&p_w1hi, g_w1hi);
    cudaGetSymbolAddress((void**)&p_w1lo, g_w1lo);
    cudaGetSymbolAddress((void**)&p_w2hi, g_w2hi);
    cudaGetSymbolAddress((void**)&p_w2lo, g_w2lo);

    cudaFuncSetAttribute(gemm_bf16x3_kernel<false>,
                         cudaFuncAttributeMaxDynamicSharedMemorySize, GSMEM);
    cudaFuncSetAttribute(gemm_bf16x3_kernel<true>,
                         cudaFuncAttributeMaxDynamicSharedMemorySize, GSMEM);

    // 0) weight splits (transposed)
    wsplit_kernel<<<dim3(N3 / 32, DMODEL / 32), 256>>>(W_aiv, p_w1hi, p_w1lo, DMODEL, N3);
    wsplit_kernel<<<dim3(DREC / 32, DMODEL / 32), 256>>>(W_mix, p_w2hi, p_w2lo, DMODEL, DREC);

    // 1) aiv = x @ W_aiv  (tcgen05 bf16x3; A split in-kernel, B via cp.async)
    gemm_bf16x3_kernel<false><<<dim3(N3 / 256, MROWS / 128), GTHREADS, GSMEM>>>(
        x, p_w1hi, p_w1lo, nullptr, p_aiv, DMODEL, N3);

    // 2) fused activation + per-chunk scan
    act_scan_kernel<<<dim3(DREC / 256, NCHUNK, BATCH), 256>>>(
        p_aiv, d_bias, p_a, p_s, p_cf, p_cdk);

    // 3) inter-chunk scan (warp-parallel)
    scan_inter_kernel<<<(BATCH * DREC * 32) / 256, 256>>>(p_cf, p_cdk, p_inc);

    // 4) replay + cross contribution -> h (fp32)
    scan_final_kernel<<<dim3(DREC / 256, NCHUNK, BATCH), 256>>>(p_a, p_s, p_inc, p_h);

    // 5) out = h @ W_mix + b_mix
    gemm_bf16x3_kernel<true><<<dim3(DREC / 256, MROWS / 128), GTHREADS, GSMEM>>>(
        p_h, p_w2hi, p_w2lo, b_mix, out, DMODEL, DREC);
}